// round 11
// baseline (speedup 1.0000x reference)
#include <cuda_runtime.h>
#include <cuda_bf16.h>
#include <cstdint>

#define BATCH 4
#define SEQ   4096
#define DIMV  1024
#define NH    16
#define DH    64
#define SDIM  128
#define ROWS  (BATCH*SEQ)   // 16384
#define BHTOT (BATCH*NH)    // 64

// ---------------- scratch (device globals: no allocation allowed) ----------------
__device__ float g_qkv [(size_t)ROWS * 3072];          // 201 MB
__device__ float g_phiq[(size_t)BHTOT * SEQ * SDIM];   // 134 MB (scale folded in)
__device__ float g_phik[(size_t)BHTOT * SEQ * SDIM];   // 134 MB
__device__ float g_beta[(size_t)BHTOT * SEQ];
__device__ float g_dv  [(size_t)BHTOT * SEQ * DH];     // 67 MB
__device__ float g_W   [(size_t)BHTOT * SDIM * DH];
__device__ float g_Wpart[(size_t)8 * BHTOT * SDIM * DH];
__device__ float g_y   [(size_t)ROWS * DIMV];          // 64 MB

// bf16 hi/lo split operands for tensor-core GEMMs
__device__ __nv_bfloat16 g_xh[(size_t)ROWS * DIMV];
__device__ __nv_bfloat16 g_xl[(size_t)ROWS * DIMV];
__device__ __nv_bfloat16 g_wqh[(size_t)3072 * DIMV];
__device__ __nv_bfloat16 g_wql[(size_t)3072 * DIMV];
__device__ __nv_bfloat16 g_woh[(size_t)DIMV * DIMV];
__device__ __nv_bfloat16 g_wol[(size_t)DIMV * DIMV];
__device__ __nv_bfloat16 g_ah[(size_t)ROWS * DIMV];
__device__ __nv_bfloat16 g_al[(size_t)ROWS * DIMV];

// ---------------- packed f32x2 helpers (Blackwell FFMA2) ----------------
__device__ __forceinline__ unsigned long long pk2(float lo, float hi) {
    unsigned long long r;
    asm("mov.b64 %0, {%1,%2};" : "=l"(r) : "f"(lo), "f"(hi));
    return r;
}
__device__ __forceinline__ void upk2(unsigned long long v, float &lo, float &hi) {
    asm("mov.b64 {%0,%1}, %2;" : "=f"(lo), "=f"(hi) : "l"(v));
}
__device__ __forceinline__ void fma2(unsigned long long &c, unsigned long long a, unsigned long long b) {
    asm("fma.rn.f32x2 %0, %1, %2, %0;" : "+l"(c) : "l"(a), "l"(b));
}

// ---------------- HMMA helpers (sm_80-class, legal on plain sm_103 target) ----------------
__device__ __forceinline__ uint32_t smem_u32(const void* p) {
    uint32_t r;
    asm("{ .reg .u64 t; cvta.to.shared.u64 t, %1; cvt.u32.u64 %0, t; }" : "=r"(r) : "l"(p));
    return r;
}
__device__ __forceinline__ void cpasync16(uint32_t dst, const void* src) {
    asm volatile("cp.async.cg.shared.global [%0], [%1], 16;" :: "r"(dst), "l"(src) : "memory");
}
#define CP_COMMIT() asm volatile("cp.async.commit_group;" ::: "memory")

__device__ __forceinline__ void ldsm4(uint32_t* r, uint32_t addr) {
    asm volatile("ldmatrix.sync.aligned.m8n8.x4.shared.b16 {%0,%1,%2,%3}, [%4];"
                 : "=r"(r[0]), "=r"(r[1]), "=r"(r[2]), "=r"(r[3]) : "r"(addr));
}
__device__ __forceinline__ void mma16816(float* c, const uint32_t* a, const uint32_t* b) {
    asm volatile("mma.sync.aligned.m16n8k16.row.col.f32.bf16.bf16.f32 "
                 "{%0,%1,%2,%3}, {%4,%5,%6,%7}, {%8,%9}, {%0,%1,%2,%3};"
                 : "+f"(c[0]), "+f"(c[1]), "+f"(c[2]), "+f"(c[3])
                 : "r"(a[0]), "r"(a[1]), "r"(a[2]), "r"(a[3]), "r"(b[0]), "r"(b[1]));
}

// CTA tile 128(M) x 256(N), warp tile 64x64 (2x4 warp grid), K-chunk 32.
// Row stride 40 bf16 (80B): 8-row ldmatrix phases step 20 banks mod 32 ->
// all 32 banks covered, conflict-free.
#define KCH    32
#define RSTR   40
#define ATILE  (128*RSTR*2)          // 10240 B
#define BTILE  (256*RSTR*2)          // 20480 B
#define BUFB   (2*ATILE + 2*BTILE)   // Ah,Al,Bh,Bl = 61440 B
#define NSTAGE 3
#define SMEMB  (NSTAGE*BUFB)         // 184320 B/CTA -> 1 CTA/SM
#define NKC    (1024/KCH)            // 32 chunks

// ============================================================================
// HMMA GEMM: C[M,N] = Ah@Bh^T + Ah@Bl^T + Al@Bh^T, fp32 out.
// A*: [M,1024] bf16 K-major. B*: [N,1024] bf16 K-major (pre-transposed).
// CTA tile 128x256, 8 warps (2x4), warp tile 64x64, K-chunk 32,
// 3-stage cp.async pipeline, ONE __syncthreads per chunk.
// EPI: += bias[col] + resid[row,col].
// ============================================================================
template<int EPI>
__global__ void __launch_bounds__(256, 1)
hmma_kernel(const __nv_bfloat16* __restrict__ Ah, const __nv_bfloat16* __restrict__ Al,
            const __nv_bfloat16* __restrict__ Bh, const __nv_bfloat16* __restrict__ Bl,
            float* __restrict__ C, int N,
            const float* __restrict__ bias, const float* __restrict__ resid)
{
    extern __shared__ char dsm[];
    const uint32_t sbase = smem_u32(dsm);
    const int tid  = threadIdx.x;
    const int lane = tid & 31, wid = tid >> 5;
    const int wm = wid >> 2, wn = wid & 3;           // warp grid 2 (m) x 4 (n)
    const int bm = blockIdx.y * 128, bn = blockIdx.x * 256;

    // ldmatrix per-lane byte offsets within a tile (RSTR-element row stride)
    const uint32_t aoffb = (uint32_t)(((wm * 64 + (lane & 15)) * RSTR + ((lane >> 4) << 3)) * 2);
    const uint32_t boffb = (uint32_t)(((wn * 64 + ((lane >> 4) << 3) + (lane & 7)) * RSTR + (lane & 8)) * 2);

    float acc[4][8][4];
    #pragma unroll
    for (int i = 0; i < 4; i++)
        #pragma unroll
        for (int j = 0; j < 8; j++)
            #pragma unroll
            for (int q = 0; q < 4; q++) acc[i][j][q] = 0.f;

    auto load_chunk = [&](int kt, int buf) {
        const uint32_t sb = sbase + buf * BUFB;
        const int kco = kt * KCH;
        #pragma unroll
        for (int i = 0; i < 2; i++) {
            const int v = tid + i * 256;                 // 0..511
            const int row = v >> 2, c4 = v & 3;          // A row 0..127, 16B chunk 0..3
            const uint32_t so = (uint32_t)((row * RSTR + c4 * 8) * 2);
            const size_t ao = (size_t)(bm + row) * 1024 + kco + c4 * 8;
            cpasync16(sb + so, Ah + ao);
            cpasync16(sb + ATILE + so, Al + ao);
        }
        #pragma unroll
        for (int i = 0; i < 4; i++) {
            const int v = tid + i * 256;                 // 0..1023
            const int row = v >> 2, c4 = v & 3;          // B row 0..255
            const uint32_t so = (uint32_t)((row * RSTR + c4 * 8) * 2);
            const size_t bo = (size_t)(bn + row) * 1024 + kco + c4 * 8;
            cpasync16(sb + 2 * ATILE + so, Bh + bo);
            cpasync16(sb + 2 * ATILE + BTILE + so, Bl + bo);
        }
        CP_COMMIT();
    };

    // prologue: two chunks in flight
    load_chunk(0, 0);
    load_chunk(1, 1);

    int rb = 0;   // buffer holding chunk kt
    int wb = 2;   // buffer to receive chunk kt+2
    #pragma unroll 1
    for (int kt = 0; kt < NKC; ++kt) {
        if (kt < NKC - 1) asm volatile("cp.async.wait_group 1;" ::: "memory");
        else              asm volatile("cp.async.wait_group 0;" ::: "memory");
        __syncthreads();                 // chunk kt visible; all warps done with kt-1
        if (kt + 2 < NKC) load_chunk(kt + 2, wb);   // overwrites buffer consumed at kt-1

        const uint32_t sb = sbase + rb * BUFB;
        #pragma unroll
        for (int ks = 0; ks < KCH / 16; ++ks) {
            uint32_t bH[8][2], bL[8][2];
            #pragma unroll
            for (int pr = 0; pr < 4; pr++) {
                const uint32_t bd = sb + 2 * ATILE + boffb + (uint32_t)((pr * 16 * RSTR + ks * 16) * 2);
                uint32_t r[4];
                ldsm4(r, bd);
                bH[pr*2][0] = r[0]; bH[pr*2][1] = r[1];
                bH[pr*2+1][0] = r[2]; bH[pr*2+1][1] = r[3];
                ldsm4(r, bd + BTILE);
                bL[pr*2][0] = r[0]; bL[pr*2][1] = r[1];
                bL[pr*2+1][0] = r[2]; bL[pr*2+1][1] = r[3];
            }
            #pragma unroll
            for (int mi = 0; mi < 4; mi++) {
                uint32_t aH[4], aL[4];
                const uint32_t ad = sb + aoffb + (uint32_t)((mi * 16 * RSTR + ks * 16) * 2);
                ldsm4(aH, ad);
                ldsm4(aL, ad + ATILE);
                #pragma unroll
                for (int ni = 0; ni < 8; ni++) {
                    mma16816(acc[mi][ni], aH, bH[ni]);
                    mma16816(acc[mi][ni], aH, bL[ni]);
                    mma16816(acc[mi][ni], aL, bH[ni]);
                }
            }
        }
        rb = (rb == 2) ? 0 : rb + 1;
        wb = (wb == 2) ? 0 : wb + 1;
    }

    // epilogue: acc frag mapping c0,c1=(m=lane/4, n=(lane%4)*2), c2,c3=(m+8)
    #pragma unroll
    for (int mi = 0; mi < 4; mi++)
        #pragma unroll
        for (int ni = 0; ni < 8; ni++) {
            const int m0 = bm + wm * 64 + mi * 16 + (lane >> 2);
            const int n0 = bn + wn * 64 + ni * 8 + (lane & 3) * 2;
            const size_t o0 = (size_t)m0 * N + n0;
            const size_t o1 = o0 + (size_t)8 * N;
            float c0 = acc[mi][ni][0], c1 = acc[mi][ni][1];
            float c2 = acc[mi][ni][2], c3 = acc[mi][ni][3];
            if (EPI) {
                const float b0v = bias[n0], b1v = bias[n0 + 1];
                c0 += b0v + resid[o0];     c1 += b1v + resid[o0 + 1];
                c2 += b0v + resid[o1];     c3 += b1v + resid[o1 + 1];
            }
            *(float2*)(C + o0) = make_float2(c0, c1);
            *(float2*)(C + o1) = make_float2(c2, c3);
        }
}

// ============================================================================
// fp32 -> bf16 hi/lo split (elementwise)
// ============================================================================
__global__ void __launch_bounds__(256)
splitx_kernel(const float* __restrict__ src, __nv_bfloat16* __restrict__ hi,
              __nv_bfloat16* __restrict__ lo)
{
    size_t idx = (size_t)blockIdx.x * 256 + threadIdx.x;
    float4 v = ((const float4*)src)[idx];
    __nv_bfloat16 h0 = __float2bfloat16(v.x), h1 = __float2bfloat16(v.y);
    __nv_bfloat16 h2 = __float2bfloat16(v.z), h3 = __float2bfloat16(v.w);
    ((__nv_bfloat162*)hi)[2 * idx]     = __halves2bfloat162(h0, h1);
    ((__nv_bfloat162*)hi)[2 * idx + 1] = __halves2bfloat162(h2, h3);
    float l0 = v.x - __bfloat162float(h0), l1 = v.y - __bfloat162float(h1);
    float l2 = v.z - __bfloat162float(h2), l3 = v.w - __bfloat162float(h3);
    ((__nv_bfloat162*)lo)[2 * idx]     = __halves2bfloat162(__float2bfloat16(l0), __float2bfloat16(l1));
    ((__nv_bfloat162*)lo)[2 * idx + 1] = __halves2bfloat162(__float2bfloat16(l2), __float2bfloat16(l3));
}

// ============================================================================
// W [1024,Ncols] fp32 -> W^T [Ncols,1024] bf16 hi/lo (transpose + split)
// ============================================================================
__global__ void __launch_bounds__(256)
wsplit_kernel(const float* __restrict__ W, __nv_bfloat16* __restrict__ hi,
              __nv_bfloat16* __restrict__ lo, int Ncols)
{
    __shared__ float t[32][33];
    const int nx = blockIdx.x * 32, ky = blockIdx.y * 32;
    const int txx = threadIdx.x & 31, tyy = threadIdx.x >> 5;   // 32 x 8
    #pragma unroll
    for (int i = 0; i < 4; i++)
        t[tyy + i * 8][txx] = W[(size_t)(ky + tyy + i * 8) * Ncols + nx + txx];
    __syncthreads();
    #pragma unroll
    for (int i = 0; i < 4; i++) {
        const int n = nx + tyy + i * 8;
        const int k = ky + txx;
        const float v = t[txx][tyy + i * 8];
        __nv_bfloat16 hh = __float2bfloat16(v);
        hi[(size_t)n * 1024 + k] = hh;
        lo[(size_t)n * 1024 + k] = __float2bfloat16(v - __bfloat162float(hh));
    }
}

// ============================================================================
// beta = x @ Wbeta + bbeta  -> g_beta[(b*16+h)*SEQ + n]
// ============================================================================
__global__ void __launch_bounds__(128)
beta_kernel(const float* __restrict__ X, const float* __restrict__ Wb,
            const float* __restrict__ bb)
{
    __shared__ float Xs[32][132];
    __shared__ float Wbs[32][16];
    const int tid = threadIdx.x;
    const int tx = tid & 3;
    const int ty = tid >> 2;
    const int bm = blockIdx.x * 128;

    unsigned long long c2[2][4];
    #pragma unroll
    for (int i = 0; i < 2; i++)
        #pragma unroll
        for (int j = 0; j < 4; j++) c2[i][j] = 0ULL;

    for (int kt = 0; kt < 32; ++kt) {
        int k0 = kt * 32;
        #pragma unroll
        for (int i = 0; i < 8; i++) {
            float4 xv = *(const float4*)(X + (size_t)(bm + tid) * DIMV + k0 + i*4);
            Xs[i*4+0][tid] = xv.x; Xs[i*4+1][tid] = xv.y;
            Xs[i*4+2][tid] = xv.z; Xs[i*4+3][tid] = xv.w;
        }
        {
            float4 wv = *(const float4*)(Wb + (size_t)(k0 + (tid >> 2)) * NH + (tid & 3) * 4);
            *(float4*)&Wbs[tid >> 2][(tid & 3) * 4] = wv;
        }
        __syncthreads();
        #pragma unroll
        for (int k = 0; k < 32; k++) {
            float4 a = *(const float4*)&Xs[k][ty*4];
            float4 b = *(const float4*)&Wbs[k][tx*4];
            unsigned long long am[2] = { pk2(a.x, a.y), pk2(a.z, a.w) };
            float bj[4] = {b.x, b.y, b.z, b.w};
            #pragma unroll
            for (int j = 0; j < 4; j++) {
                unsigned long long b2 = pk2(bj[j], bj[j]);
                fma2(c2[0][j], am[0], b2);
                fma2(c2[1][j], am[1], b2);
            }
        }
        __syncthreads();
    }

    #pragma unroll
    for (int i = 0; i < 2; i++) {
        float vv[2][4];
        #pragma unroll
        for (int j = 0; j < 4; j++) upk2(c2[i][j], vv[0][j], vv[1][j]);
        #pragma unroll
        for (int hh = 0; hh < 2; hh++) {
            int r = bm + ty*4 + 2*i + hh;
            int b = r >> 12, n = r & 4095;
            #pragma unroll
            for (int j = 0; j < 4; j++) {
                int h = tx*4 + j;
                g_beta[(size_t)(b*NH + h) * SEQ + n] = vv[hh][j] + bb[h];
            }
        }
    }
}

// ============================================================================
// dpfp feature maps (L1-normalized; q gets SCALE folded)
// ============================================================================
__global__ void __launch_bounds__(256)
dpfp_kernel()
{
    __shared__ float cat[8][128];
    const int tid = threadIdx.x;
    const int w = tid >> 5, l = tid & 31;
    unsigned int task = blockIdx.x * 8u + w;   // < 524288
    int qk = task >> 18;
    unsigned int rem = task & 0x3FFFFu;
    int bh = rem >> 12;
    int n  = rem & 4095;
    int b = bh >> 4, h = bh & 15;

    const float* src = g_qkv + (size_t)(b*SEQ + n) * 3072 + qk * 1024 + h * DH;
    float f0 = src[l];
    float f1 = src[l + 32];
    cat[w][l]      = fmaxf(f0, 0.f);
    cat[w][l + 32] = fmaxf(f1, 0.f);
    cat[w][l + 64] = fmaxf(-f0, 0.f);
    cat[w][l + 96] = fmaxf(-f1, 0.f);
    __syncwarp();
    float p0 = cat[w][l]      * cat[w][(l + 127) & 127];
    float p1 = cat[w][l + 32] * cat[w][l + 31];
    float p2 = cat[w][l + 64] * cat[w][l + 63];
    float p3 = cat[w][l + 96] * cat[w][l + 95];
    float s = p0 + p1 + p2 + p3;
    #pragma unroll
    for (int o = 16; o; o >>= 1) s += __shfl_xor_sync(0xffffffffu, s, o);
    float inv = 1.0f / s;
    float* dst;
    if (qk == 0) { inv *= 0.125f; dst = g_phiq; }
    else         { dst = g_phik; }
    dst += (size_t)(bh * SEQ + n) * SDIM;
    dst[l]      = p0 * inv;
    dst[l + 32] = p1 * inv;
    dst[l + 64] = p2 * inv;
    dst[l + 96] = p3 * inv;
}

// ============================================================================
// phiw: per-(b,h) GEMM [128n x 128s] @ [128s x 64d], W resident in shared.
// MODE 0: dv = beta * (v - phik@W0)
// MODE 1: attn = phiq_scaled @ W  -> bf16 hi/lo splits (feeds hmma<1>)
// ============================================================================
template<int MODE>
__global__ void __launch_bounds__(256)
phiw_kernel(const float* __restrict__ WmIn)
{
    __shared__ float Ws[128][68];
    __shared__ float As[16][132];
    const int tid = threadIdx.x;
    const int tx = tid & 15, ty = tid >> 4;
    const int bh = blockIdx.y;
    const int n0 = blockIdx.x * 128;

    const float* wsrc = (MODE == 0 ? WmIn : (const float*)g_W) + (size_t)bh * (SDIM*DH);
    #pragma unroll
    for (int i = 0; i < 8; i++) {
        int v = tid + i*256;
        int row = v >> 4, c4 = (v & 15) << 2;
        *(float4*)&Ws[row][c4] = *(const float4*)(wsrc + row*DH + c4);
    }
    const float* phib = (MODE == 0 ? g_phik : g_phiq) + (size_t)(bh*SEQ + n0) * SDIM;
    const int arow = tid >> 2, ac4 = (tid & 3) << 2;

    unsigned long long c2[4][4];
    #pragma unroll
    for (int i = 0; i < 4; i++)
        #pragma unroll
        for (int j = 0; j < 4; j++) c2[i][j] = 0ULL;

    for (int kt = 0; kt < 8; ++kt) {
        int k0 = kt * 16;
        float4 v0 = *(const float4*)(phib + (size_t)arow        * SDIM + k0 + ac4);
        float4 v1 = *(const float4*)(phib + (size_t)(arow + 64) * SDIM + k0 + ac4);
        As[ac4+0][arow]    = v0.x; As[ac4+1][arow]    = v0.y;
        As[ac4+2][arow]    = v0.z; As[ac4+3][arow]    = v0.w;
        As[ac4+0][arow+64] = v1.x; As[ac4+1][arow+64] = v1.y;
        As[ac4+2][arow+64] = v1.z; As[ac4+3][arow+64] = v1.w;
        __syncthreads();
        #pragma unroll
        for (int k = 0; k < 16; k++) {
            float4 a0 = *(const float4*)&As[k][ty*8];
            float4 a1 = *(const float4*)&As[k][ty*8+4];
            float4 bq = *(const float4*)&Ws[k0 + k][tx*4];
            unsigned long long am[4];
            am[0] = pk2(a0.x, a0.y); am[1] = pk2(a0.z, a0.w);
            am[2] = pk2(a1.x, a1.y); am[3] = pk2(a1.z, a1.w);
            float bj[4] = {bq.x, bq.y, bq.z, bq.w};
            #pragma unroll
            for (int j = 0; j < 4; j++) {
                unsigned long long bb = pk2(bj[j], bj[j]);
                fma2(c2[0][j], am[0], bb);
                fma2(c2[1][j], am[1], bb);
                fma2(c2[2][j], am[2], bb);
                fma2(c2[3][j], am[3], bb);
            }
        }
        __syncthreads();
    }

    const int h = bh & 15, b = bh >> 4;
    #pragma unroll
    for (int i = 0; i < 4; i++) {
        float vv[2][4];
        #pragma unroll
        for (int j = 0; j < 4; j++) upk2(c2[i][j], vv[0][j], vv[1][j]);
        #pragma unroll
        for (int hh = 0; hh < 2; hh++) {
            int n = n0 + ty*8 + 2*i + hh;
            int d0 = tx*4;
            if (MODE == 0) {
                float bt = g_beta[(size_t)bh * SEQ + n];
                float4 v4 = *(const float4*)(g_qkv + (size_t)(b*SEQ + n) * 3072 + 2048 + h*DH + d0);
                float4 o;
                o.x = bt * (v4.x - vv[hh][0]);
                o.y = bt * (v4.y - vv[hh][1]);
                o.z = bt * (v4.z - vv[hh][2]);
                o.w = bt * (v4.w - vv[hh][3]);
                *(float4*)(g_dv + (size_t)(bh*SEQ + n) * DH + d0) = o;
            } else {
                size_t base = (size_t)(b*SEQ + n) * DIMV + h*DH + d0;
                #pragma unroll
                for (int j = 0; j < 4; j += 2) {
                    float x0 = vv[hh][j], x1 = vv[hh][j+1];
                    __nv_bfloat16 h0 = __float2bfloat16(x0), h1 = __float2bfloat16(x1);
                    float l0 = x0 - __bfloat162float(h0), l1 = x1 - __bfloat162float(h1);
                    *(__nv_bfloat162*)(g_ah + base + j) = __halves2bfloat162(h0, h1);
                    *(__nv_bfloat162*)(g_al + base + j) =
                        __halves2bfloat162(__float2bfloat16(l0), __float2bfloat16(l1));
                }
            }
        }
    }
}

// ============================================================================
// wacc: partial W[s,d] = sum_n phik[n,s]*dv[n,d]; then deterministic reduce.
// ============================================================================
__global__ void __launch_bounds__(256)
wacc_kernel()
{
    __shared__ float Ph[32][132];
    __shared__ float Dvs[32][68];
    const int tid = threadIdx.x;
    const int ts = tid >> 4, td = tid & 15;
    const int bh = blockIdx.y;
    const int n0 = blockIdx.x * 512;

    unsigned long long c2[4][4];
    #pragma unroll
    for (int i = 0; i < 4; i++)
        #pragma unroll
        for (int j = 0; j < 4; j++) c2[i][j] = 0ULL;

    for (int nt = 0; nt < 16; ++nt) {
        int nb = n0 + nt * 32;
        #pragma unroll
        for (int i = 0; i < 4; i++) {
            int v = tid + i*256;
            int row = v >> 5, c4 = (v & 31) << 2;
            *(float4*)&Ph[row][c4] =
                *(const float4*)(g_phik + (size_t)(bh*SEQ + nb + row) * SDIM + c4);
        }
        #pragma unroll
        for (int i = 0; i < 2; i++) {
            int v = tid + i*256;
            int row = v >> 4, c4 = (v & 15) << 2;
            *(float4*)&Dvs[row][c4] =
                *(const float4*)(g_dv + (size_t)(bh*SEQ + nb + row) * DH + c4);
        }
        __syncthreads();
        #pragma unroll
        for (int nn = 0; nn < 32; ++nn) {
            float4 a0 = *(const float4*)&Ph[nn][ts*8];
            float4 a1 = *(const float4*)&Ph[nn][ts*8+4];
            float4 dq = *(const float4*)&Dvs[nn][td*4];
            unsigned long long am[4];
            am[0] = pk2(a0.x, a0.y); am[1] = pk2(a0.z, a0.w);
            am[2] = pk2(a1.x, a1.y); am[3] = pk2(a1.z, a1.w);
            float dj[4] = {dq.x, dq.y, dq.z, dq.w};
            #pragma unroll
            for (int j = 0; j < 4; j++) {
                unsigned long long bb = pk2(dj[j], dj[j]);
                fma2(c2[0][j], am[0], bb);
                fma2(c2[1][j], am[1], bb);
                fma2(c2[2][j], am[2], bb);
                fma2(c2[3][j], am[3], bb);
            }
        }
        __syncthreads();
    }

    float* wp = g_Wpart + ((size_t)blockIdx.x * BHTOT + bh) * (SDIM*DH);
    #pragma unroll
    for (int i = 0; i < 4; i++) {
        float vv[2][4];
        #pragma unroll
        for (int j = 0; j < 4; j++) upk2(c2[i][j], vv[0][j], vv[1][j]);
        #pragma unroll
        for (int hh = 0; hh < 2; hh++) {
            int s = ts*8 + 2*i + hh;
            *(float4*)(wp + s*DH + td*4) =
                make_float4(vv[hh][0], vv[hh][1], vv[hh][2], vv[hh][3]);
        }
    }
}

__global__ void __launch_bounds__(256)
wreduce_kernel(const float* __restrict__ W0)
{
    int idx = blockIdx.x * 256 + threadIdx.x;   // < 524288
    float s = W0[idx];
    #pragma unroll
    for (int c = 0; c < 8; c++) s += g_Wpart[(size_t)c * (BHTOT*SDIM*DH) + idx];
    g_W[idx] = s;
}

// ============================================================================
// LayerNorm over 1024, one row per block.
// ============================================================================
__global__ void __launch_bounds__(256)
ln_kernel(const float* __restrict__ gamma, const float* __restrict__ betaln,
          float* __restrict__ out)
{
    const int row = blockIdx.x, tid = threadIdx.x;
    float4 v = *(const float4*)(g_y + (size_t)row * DIMV + tid*4);
    float s = v.x + v.y + v.z + v.w;
    float q = v.x*v.x + v.y*v.y + v.z*v.z + v.w*v.w;
    #pragma unroll
    for (int o = 16; o; o >>= 1) {
        s += __shfl_xor_sync(0xffffffffu, s, o);
        q += __shfl_xor_sync(0xffffffffu, q, o);
    }
    __shared__ float ss[8], qq[8];
    int w = tid >> 5, l = tid & 31;
    if (l == 0) { ss[w] = s; qq[w] = q; }
    __syncthreads();
    float st = 0.f, qt = 0.f;
    #pragma unroll
    for (int i = 0; i < 8; i++) { st += ss[i]; qt += qq[i]; }
    float mu = st * (1.0f / DIMV);
    float var = qt * (1.0f / DIMV) - mu * mu;
    float rs = rsqrtf(var + 1e-5f);
    float4 g = *(const float4*)(gamma + tid*4);
    float4 bb = *(const float4*)(betaln + tid*4);
    float4 o;
    o.x = (v.x - mu) * rs * g.x + bb.x;
    o.y = (v.y - mu) * rs * g.y + bb.y;
    o.z = (v.z - mu) * rs * g.z + bb.z;
    o.w = (v.w - mu) * rs * g.w + bb.w;
    *(float4*)(out + (size_t)row * DIMV + tid*4) = o;
}

// ============================================================================
extern "C" void kernel_launch(void* const* d_in, const int* in_sizes, int n_in,
                              void* d_out, int out_size)
{
    (void)in_sizes; (void)n_in; (void)out_size;
    const float* x      = (const float*)d_in[0];
    const float* Wqkv   = (const float*)d_in[1];
    const float* Wbeta  = (const float*)d_in[2];
    const float* bbeta  = (const float*)d_in[3];
    const float* Wout   = (const float*)d_in[4];
    const float* bout   = (const float*)d_in[5];
    const float* gamma  = (const float*)d_in[6];
    const float* betaln = (const float*)d_in[7];
    const float* W0     = (const float*)d_in[8];
    float* out = (float*)d_out;

    float *p_qkv = nullptr, *p_y = nullptr;
    cudaGetSymbolAddress((void**)&p_qkv, g_qkv);
    cudaGetSymbolAddress((void**)&p_y,   g_y);
    __nv_bfloat16 *p_xh, *p_xl, *p_wqh, *p_wql, *p_woh, *p_wol, *p_ah, *p_al;
    cudaGetSymbolAddress((void**)&p_xh,  g_xh);
    cudaGetSymbolAddress((void**)&p_xl,  g_xl);
    cudaGetSymbolAddress((void**)&p_wqh, g_wqh);
    cudaGetSymbolAddress((void**)&p_wql, g_wql);
    cudaGetSymbolAddress((void**)&p_woh, g_woh);
    cudaGetSymbolAddress((void**)&p_wol, g_wol);
    cudaGetSymbolAddress((void**)&p_ah,  g_ah);
    cudaGetSymbolAddress((void**)&p_al,  g_al);

    cudaFuncSetAttribute(hmma_kernel<0>, cudaFuncAttributeMaxDynamicSharedMemorySize, SMEMB);
    cudaFuncSetAttribute(hmma_kernel<1>, cudaFuncAttributeMaxDynamicSharedMemorySize, SMEMB);

    // 0. bf16 hi/lo operand prep
    splitx_kernel<<<16384, 256>>>(x, p_xh, p_xl);
    wsplit_kernel<<<dim3(96, 32), 256>>>(Wqkv, p_wqh, p_wql, 3072);
    wsplit_kernel<<<dim3(32, 32), 256>>>(Wout, p_woh, p_wol, 1024);
    // 1. qkv = x @ Wqkv   (HMMA, 3-split bf16, warp tile 64x64)
    hmma_kernel<0><<<dim3(12, 128), 256, SMEMB>>>(
        p_xh, p_xl, p_wqh, p_wql, p_qkv, 3072, nullptr, nullptr);
    // 2. beta = x @ Wbeta + bbeta
    beta_kernel<<<128, 128>>>(x, Wbeta, bbeta);
    // 3. dpfp feature maps
    dpfp_kernel<<<65536, 256>>>();
    // 4a. dv = beta * (v - phik @ W0)
    phiw_kernel<0><<<dim3(32, 64), 256>>>(W0);
    // 4b. W = W0 + phik^T @ dv
    wacc_kernel<<<dim3(8, 64), 256>>>();
    wreduce_kernel<<<2048, 256>>>(W0);
    // 4c. attn = phiq_scaled @ W  -> bf16 hi/lo
    phiw_kernel<1><<<dim3(32, 64), 256>>>(nullptr);
    // 5. y = attn @ Wout + bout + x   (HMMA)
    hmma_kernel<1><<<dim3(4, 128), 256, SMEMB>>>(
        p_ah, p_al, p_woh, p_wol, p_y, 1024, bout, x);
    // 6. LayerNorm -> out
    ln_kernel<<<16384, 256>>>(gamma, betaln, out);
}

// round 12
// speedup vs baseline: 1.1118x; 1.1118x over previous
#include <cuda_runtime.h>
#include <cuda_bf16.h>
#include <cstdint>

#define BATCH 4
#define SEQ   4096
#define DIMV  1024
#define NH    16
#define DH    64
#define SDIM  128
#define ROWS  (BATCH*SEQ)   // 16384
#define BHTOT (BATCH*NH)    // 64

// ---------------- scratch (device globals: no allocation allowed) ----------------
__device__ float g_qkv [(size_t)ROWS * 3072];          // 201 MB
__device__ float g_phiq[(size_t)BHTOT * SEQ * SDIM];   // 134 MB (scale folded in)
__device__ float g_phik[(size_t)BHTOT * SEQ * SDIM];   // 134 MB
__device__ float g_beta[(size_t)BHTOT * SEQ];
__device__ float g_dv  [(size_t)BHTOT * SEQ * DH];     // 67 MB
__device__ float g_W   [(size_t)BHTOT * SDIM * DH];
__device__ float g_Wpart[(size_t)8 * BHTOT * SDIM * DH];
__device__ float g_y   [(size_t)ROWS * DIMV];          // 64 MB

// bf16 hi/lo split operands for tensor-core GEMMs
__device__ __nv_bfloat16 g_xh[(size_t)ROWS * DIMV];
__device__ __nv_bfloat16 g_xl[(size_t)ROWS * DIMV];
__device__ __nv_bfloat16 g_wqh[(size_t)3072 * DIMV];
__device__ __nv_bfloat16 g_wql[(size_t)3072 * DIMV];
__device__ __nv_bfloat16 g_woh[(size_t)DIMV * DIMV];
__device__ __nv_bfloat16 g_wol[(size_t)DIMV * DIMV];
__device__ __nv_bfloat16 g_ah[(size_t)ROWS * DIMV];
__device__ __nv_bfloat16 g_al[(size_t)ROWS * DIMV];

// ---------------- packed f32x2 helpers (Blackwell FFMA2) ----------------
__device__ __forceinline__ unsigned long long pk2(float lo, float hi) {
    unsigned long long r;
    asm("mov.b64 %0, {%1,%2};" : "=l"(r) : "f"(lo), "f"(hi));
    return r;
}
__device__ __forceinline__ void upk2(unsigned long long v, float &lo, float &hi) {
    asm("mov.b64 {%0,%1}, %2;" : "=f"(lo), "=f"(hi) : "l"(v));
}
__device__ __forceinline__ void fma2(unsigned long long &c, unsigned long long a, unsigned long long b) {
    asm("fma.rn.f32x2 %0, %1, %2, %0;" : "+l"(c) : "l"(a), "l"(b));
}

// ---------------- HMMA helpers (sm_80-class, legal on plain sm_103 target) ----------------
__device__ __forceinline__ uint32_t smem_u32(const void* p) {
    uint32_t r;
    asm("{ .reg .u64 t; cvta.to.shared.u64 t, %1; cvt.u32.u64 %0, t; }" : "=r"(r) : "l"(p));
    return r;
}
__device__ __forceinline__ void cpasync16(uint32_t dst, const void* src) {
    asm volatile("cp.async.cg.shared.global [%0], [%1], 16;" :: "r"(dst), "l"(src) : "memory");
}
#define CP_COMMIT() asm volatile("cp.async.commit_group;" ::: "memory")

__device__ __forceinline__ void ldsm4(uint32_t* r, uint32_t addr) {
    asm volatile("ldmatrix.sync.aligned.m8n8.x4.shared.b16 {%0,%1,%2,%3}, [%4];"
                 : "=r"(r[0]), "=r"(r[1]), "=r"(r[2]), "=r"(r[3]) : "r"(addr));
}
__device__ __forceinline__ void mma16816(float* c, const uint32_t* a, const uint32_t* b) {
    asm volatile("mma.sync.aligned.m16n8k16.row.col.f32.bf16.bf16.f32 "
                 "{%0,%1,%2,%3}, {%4,%5,%6,%7}, {%8,%9}, {%0,%1,%2,%3};"
                 : "+f"(c[0]), "+f"(c[1]), "+f"(c[2]), "+f"(c[3])
                 : "r"(a[0]), "r"(a[1]), "r"(a[2]), "r"(a[3]), "r"(b[0]), "r"(b[1]));
}

// K-chunk 32, row stride 40 bf16 (80B): 8-row ldmatrix phases step 20 banks
// mod 32 -> all 32 banks covered, conflict-free.
#define KCH    32
#define RSTR   40
#define TILEB  (128*RSTR*2)          // 10240 B
#define BUFB   (4*TILEB)             // Ah,Al,Bh,Bl = 40960 B
#define NSTAGE 2
#define SMEMB  (NSTAGE*BUFB)         // 81920 B/CTA -> 2 CTAs/SM
#define NKC    (1024/KCH)            // 32 chunks

// ============================================================================
// HMMA GEMM: C[M,N] = Ah@Bh^T + Ah@Bl^T + Al@Bh^T, fp32 out.
// A*: [M,1024] bf16 K-major. B*: [N,1024] bf16 K-major (pre-transposed).
// CTA tile 128x128, 8 warps (2x4), warp tile 64x32, K-chunk 32,
// 2-stage cp.async pipeline, ONE __syncthreads per chunk, 2 CTAs/SM.
// Split-term MMAs are issued term-outer so writers of the same accumulator
// are separated by 4 independent MMAs (no acc-RAW back-to-back).
// EPI: += bias[col] + resid[row,col].
// ============================================================================
template<int EPI>
__global__ void __launch_bounds__(256, 2)
hmma_kernel(const __nv_bfloat16* __restrict__ Ah, const __nv_bfloat16* __restrict__ Al,
            const __nv_bfloat16* __restrict__ Bh, const __nv_bfloat16* __restrict__ Bl,
            float* __restrict__ C, int N,
            const float* __restrict__ bias, const float* __restrict__ resid)
{
    extern __shared__ char dsm[];
    const uint32_t sbase = smem_u32(dsm);
    const int tid  = threadIdx.x;
    const int lane = tid & 31, wid = tid >> 5;
    const int wm = wid >> 2, wn = wid & 3;           // warp grid 2 (m) x 4 (n)
    const int bm = blockIdx.y * 128, bn = blockIdx.x * 128;

    // ldmatrix per-lane byte offsets within a tile (RSTR-element row stride)
    const uint32_t aoffb = (uint32_t)(((wm * 64 + (lane & 15)) * RSTR + ((lane >> 4) << 3)) * 2);
    const uint32_t boffb = (uint32_t)(((wn * 32 + ((lane >> 4) << 3) + (lane & 7)) * RSTR + (lane & 8)) * 2);

    float acc[4][4][4];
    #pragma unroll
    for (int i = 0; i < 4; i++)
        #pragma unroll
        for (int j = 0; j < 4; j++)
            #pragma unroll
            for (int q = 0; q < 4; q++) acc[i][j][q] = 0.f;

    auto load_chunk = [&](int kt, int buf) {
        const uint32_t sb = sbase + buf * BUFB;
        const int kco = kt * KCH;
        #pragma unroll
        for (int i = 0; i < 2; i++) {
            const int v = tid + i * 256;                 // 0..511
            const int row = v >> 2, c4 = v & 3;          // row 0..127, 16B chunk 0..3
            const uint32_t so = (uint32_t)((row * RSTR + c4 * 8) * 2);
            const size_t ao = (size_t)(bm + row) * 1024 + kco + c4 * 8;
            const size_t bo = (size_t)(bn + row) * 1024 + kco + c4 * 8;
            cpasync16(sb + 0 * TILEB + so, Ah + ao);
            cpasync16(sb + 1 * TILEB + so, Al + ao);
            cpasync16(sb + 2 * TILEB + so, Bh + bo);
            cpasync16(sb + 3 * TILEB + so, Bl + bo);
        }
        CP_COMMIT();
    };

    load_chunk(0, 0);

    #pragma unroll 1
    for (int kt = 0; kt < NKC; ++kt) {
        const int rb = kt & 1;
        asm volatile("cp.async.wait_group 0;" ::: "memory");   // chunk kt landed
        __syncthreads();                                       // all warps done with kt-1's buffer
        if (kt + 1 < NKC) load_chunk(kt + 1, rb ^ 1);          // overlaps compute of kt

        const uint32_t sb = sbase + rb * BUFB;
        #pragma unroll
        for (int ks = 0; ks < KCH / 16; ++ks) {
            // B fragments (16 regs), A fragments per mi-pair
            uint32_t bH[4][2], bL[4][2];
            #pragma unroll
            for (int pr = 0; pr < 2; pr++) {
                const uint32_t bd = sb + 2 * TILEB + boffb + (uint32_t)((pr * 16 * RSTR + ks * 16) * 2);
                uint32_t r[4];
                ldsm4(r, bd);
                bH[pr*2][0] = r[0]; bH[pr*2][1] = r[1];
                bH[pr*2+1][0] = r[2]; bH[pr*2+1][1] = r[3];
                ldsm4(r, bd + TILEB);
                bL[pr*2][0] = r[0]; bL[pr*2][1] = r[1];
                bL[pr*2+1][0] = r[2]; bL[pr*2+1][1] = r[3];
            }
            #pragma unroll
            for (int mi = 0; mi < 4; mi++) {
                uint32_t aH[4], aL[4];
                const uint32_t ad = sb + aoffb + (uint32_t)((mi * 16 * RSTR + ks * 16) * 2);
                ldsm4(aH, ad);
                ldsm4(aL, ad + TILEB);
                // term-outer: writers of acc[mi][ni] are 4 MMAs apart
                #pragma unroll
                for (int ni = 0; ni < 4; ni++) mma16816(acc[mi][ni], aH, bH[ni]);
                #pragma unroll
                for (int ni = 0; ni < 4; ni++) mma16816(acc[mi][ni], aH, bL[ni]);
                #pragma unroll
                for (int ni = 0; ni < 4; ni++) mma16816(acc[mi][ni], aL, bH[ni]);
            }
        }
    }

    // epilogue: acc frag mapping c0,c1=(m=lane/4, n=(lane%4)*2), c2,c3=(m+8)
    #pragma unroll
    for (int mi = 0; mi < 4; mi++)
        #pragma unroll
        for (int ni = 0; ni < 4; ni++) {
            const int m0 = bm + wm * 64 + mi * 16 + (lane >> 2);
            const int n0 = bn + wn * 32 + ni * 8 + (lane & 3) * 2;
            const size_t o0 = (size_t)m0 * N + n0;
            const size_t o1 = o0 + (size_t)8 * N;
            float c0 = acc[mi][ni][0], c1 = acc[mi][ni][1];
            float c2 = acc[mi][ni][2], c3 = acc[mi][ni][3];
            if (EPI) {
                const float b0v = bias[n0], b1v = bias[n0 + 1];
                c0 += b0v + resid[o0];     c1 += b1v + resid[o0 + 1];
                c2 += b0v + resid[o1];     c3 += b1v + resid[o1 + 1];
            }
            *(float2*)(C + o0) = make_float2(c0, c1);
            *(float2*)(C + o1) = make_float2(c2, c3);
        }
}

// ============================================================================
// fp32 -> bf16 hi/lo split (elementwise)
// ============================================================================
__global__ void __launch_bounds__(256)
splitx_kernel(const float* __restrict__ src, __nv_bfloat16* __restrict__ hi,
              __nv_bfloat16* __restrict__ lo)
{
    size_t idx = (size_t)blockIdx.x * 256 + threadIdx.x;
    float4 v = ((const float4*)src)[idx];
    __nv_bfloat16 h0 = __float2bfloat16(v.x), h1 = __float2bfloat16(v.y);
    __nv_bfloat16 h2 = __float2bfloat16(v.z), h3 = __float2bfloat16(v.w);
    ((__nv_bfloat162*)hi)[2 * idx]     = __halves2bfloat162(h0, h1);
    ((__nv_bfloat162*)hi)[2 * idx + 1] = __halves2bfloat162(h2, h3);
    float l0 = v.x - __bfloat162float(h0), l1 = v.y - __bfloat162float(h1);
    float l2 = v.z - __bfloat162float(h2), l3 = v.w - __bfloat162float(h3);
    ((__nv_bfloat162*)lo)[2 * idx]     = __halves2bfloat162(__float2bfloat16(l0), __float2bfloat16(l1));
    ((__nv_bfloat162*)lo)[2 * idx + 1] = __halves2bfloat162(__float2bfloat16(l2), __float2bfloat16(l3));
}

// ============================================================================
// W [1024,Ncols] fp32 -> W^T [Ncols,1024] bf16 hi/lo (transpose + split)
// ============================================================================
__global__ void __launch_bounds__(256)
wsplit_kernel(const float* __restrict__ W, __nv_bfloat16* __restrict__ hi,
              __nv_bfloat16* __restrict__ lo, int Ncols)
{
    __shared__ float t[32][33];
    const int nx = blockIdx.x * 32, ky = blockIdx.y * 32;
    const int txx = threadIdx.x & 31, tyy = threadIdx.x >> 5;   // 32 x 8
    #pragma unroll
    for (int i = 0; i < 4; i++)
        t[tyy + i * 8][txx] = W[(size_t)(ky + tyy + i * 8) * Ncols + nx + txx];
    __syncthreads();
    #pragma unroll
    for (int i = 0; i < 4; i++) {
        const int n = nx + tyy + i * 8;
        const int k = ky + txx;
        const float v = t[txx][tyy + i * 8];
        __nv_bfloat16 hh = __float2bfloat16(v);
        hi[(size_t)n * 1024 + k] = hh;
        lo[(size_t)n * 1024 + k] = __float2bfloat16(v - __bfloat162float(hh));
    }
}

// ============================================================================
// beta = x @ Wbeta + bbeta  -> g_beta[(b*16+h)*SEQ + n]
// ============================================================================
__global__ void __launch_bounds__(128)
beta_kernel(const float* __restrict__ X, const float* __restrict__ Wb,
            const float* __restrict__ bb)
{
    __shared__ float Xs[32][132];
    __shared__ float Wbs[32][16];
    const int tid = threadIdx.x;
    const int tx = tid & 3;
    const int ty = tid >> 2;
    const int bm = blockIdx.x * 128;

    unsigned long long c2[2][4];
    #pragma unroll
    for (int i = 0; i < 2; i++)
        #pragma unroll
        for (int j = 0; j < 4; j++) c2[i][j] = 0ULL;

    for (int kt = 0; kt < 32; ++kt) {
        int k0 = kt * 32;
        #pragma unroll
        for (int i = 0; i < 8; i++) {
            float4 xv = *(const float4*)(X + (size_t)(bm + tid) * DIMV + k0 + i*4);
            Xs[i*4+0][tid] = xv.x; Xs[i*4+1][tid] = xv.y;
            Xs[i*4+2][tid] = xv.z; Xs[i*4+3][tid] = xv.w;
        }
        {
            float4 wv = *(const float4*)(Wb + (size_t)(k0 + (tid >> 2)) * NH + (tid & 3) * 4);
            *(float4*)&Wbs[tid >> 2][(tid & 3) * 4] = wv;
        }
        __syncthreads();
        #pragma unroll
        for (int k = 0; k < 32; k++) {
            float4 a = *(const float4*)&Xs[k][ty*4];
            float4 b = *(const float4*)&Wbs[k][tx*4];
            unsigned long long am[2] = { pk2(a.x, a.y), pk2(a.z, a.w) };
            float bj[4] = {b.x, b.y, b.z, b.w};
            #pragma unroll
            for (int j = 0; j < 4; j++) {
                unsigned long long b2 = pk2(bj[j], bj[j]);
                fma2(c2[0][j], am[0], b2);
                fma2(c2[1][j], am[1], b2);
            }
        }
        __syncthreads();
    }

    #pragma unroll
    for (int i = 0; i < 2; i++) {
        float vv[2][4];
        #pragma unroll
        for (int j = 0; j < 4; j++) upk2(c2[i][j], vv[0][j], vv[1][j]);
        #pragma unroll
        for (int hh = 0; hh < 2; hh++) {
            int r = bm + ty*4 + 2*i + hh;
            int b = r >> 12, n = r & 4095;
            #pragma unroll
            for (int j = 0; j < 4; j++) {
                int h = tx*4 + j;
                g_beta[(size_t)(b*NH + h) * SEQ + n] = vv[hh][j] + bb[h];
            }
        }
    }
}

// ============================================================================
// dpfp feature maps (L1-normalized; q gets SCALE folded)
// ============================================================================
__global__ void __launch_bounds__(256)
dpfp_kernel()
{
    __shared__ float cat[8][128];
    const int tid = threadIdx.x;
    const int w = tid >> 5, l = tid & 31;
    unsigned int task = blockIdx.x * 8u + w;   // < 524288
    int qk = task >> 18;
    unsigned int rem = task & 0x3FFFFu;
    int bh = rem >> 12;
    int n  = rem & 4095;
    int b = bh >> 4, h = bh & 15;

    const float* src = g_qkv + (size_t)(b*SEQ + n) * 3072 + qk * 1024 + h * DH;
    float f0 = src[l];
    float f1 = src[l + 32];
    cat[w][l]      = fmaxf(f0, 0.f);
    cat[w][l + 32] = fmaxf(f1, 0.f);
    cat[w][l + 64] = fmaxf(-f0, 0.f);
    cat[w][l + 96] = fmaxf(-f1, 0.f);
    __syncwarp();
    float p0 = cat[w][l]      * cat[w][(l + 127) & 127];
    float p1 = cat[w][l + 32] * cat[w][l + 31];
    float p2 = cat[w][l + 64] * cat[w][l + 63];
    float p3 = cat[w][l + 96] * cat[w][l + 95];
    float s = p0 + p1 + p2 + p3;
    #pragma unroll
    for (int o = 16; o; o >>= 1) s += __shfl_xor_sync(0xffffffffu, s, o);
    float inv = 1.0f / s;
    float* dst;
    if (qk == 0) { inv *= 0.125f; dst = g_phiq; }
    else         { dst = g_phik; }
    dst += (size_t)(bh * SEQ + n) * SDIM;
    dst[l]      = p0 * inv;
    dst[l + 32] = p1 * inv;
    dst[l + 64] = p2 * inv;
    dst[l + 96] = p3 * inv;
}

// ============================================================================
// phiw: per-(b,h) GEMM [128n x 128s] @ [128s x 64d], W resident in shared.
// MODE 0: dv = beta * (v - phik@W0)
// MODE 1: attn = phiq_scaled @ W  -> bf16 hi/lo splits (feeds hmma<1>)
// ============================================================================
template<int MODE>
__global__ void __launch_bounds__(256)
phiw_kernel(const float* __restrict__ WmIn)
{
    __shared__ float Ws[128][68];
    __shared__ float As[16][132];
    const int tid = threadIdx.x;
    const int tx = tid & 15, ty = tid >> 4;
    const int bh = blockIdx.y;
    const int n0 = blockIdx.x * 128;

    const float* wsrc = (MODE == 0 ? WmIn : (const float*)g_W) + (size_t)bh * (SDIM*DH);
    #pragma unroll
    for (int i = 0; i < 8; i++) {
        int v = tid + i*256;
        int row = v >> 4, c4 = (v & 15) << 2;
        *(float4*)&Ws[row][c4] = *(const float4*)(wsrc + row*DH + c4);
    }
    const float* phib = (MODE == 0 ? g_phik : g_phiq) + (size_t)(bh*SEQ + n0) * SDIM;
    const int arow = tid >> 2, ac4 = (tid & 3) << 2;

    unsigned long long c2[4][4];
    #pragma unroll
    for (int i = 0; i < 4; i++)
        #pragma unroll
        for (int j = 0; j < 4; j++) c2[i][j] = 0ULL;

    for (int kt = 0; kt < 8; ++kt) {
        int k0 = kt * 16;
        float4 v0 = *(const float4*)(phib + (size_t)arow        * SDIM + k0 + ac4);
        float4 v1 = *(const float4*)(phib + (size_t)(arow + 64) * SDIM + k0 + ac4);
        As[ac4+0][arow]    = v0.x; As[ac4+1][arow]    = v0.y;
        As[ac4+2][arow]    = v0.z; As[ac4+3][arow]    = v0.w;
        As[ac4+0][arow+64] = v1.x; As[ac4+1][arow+64] = v1.y;
        As[ac4+2][arow+64] = v1.z; As[ac4+3][arow+64] = v1.w;
        __syncthreads();
        #pragma unroll
        for (int k = 0; k < 16; k++) {
            float4 a0 = *(const float4*)&As[k][ty*8];
            float4 a1 = *(const float4*)&As[k][ty*8+4];
            float4 bq = *(const float4*)&Ws[k0 + k][tx*4];
            unsigned long long am[4];
            am[0] = pk2(a0.x, a0.y); am[1] = pk2(a0.z, a0.w);
            am[2] = pk2(a1.x, a1.y); am[3] = pk2(a1.z, a1.w);
            float bj[4] = {bq.x, bq.y, bq.z, bq.w};
            #pragma unroll
            for (int j = 0; j < 4; j++) {
                unsigned long long bb = pk2(bj[j], bj[j]);
                fma2(c2[0][j], am[0], bb);
                fma2(c2[1][j], am[1], bb);
                fma2(c2[2][j], am[2], bb);
                fma2(c2[3][j], am[3], bb);
            }
        }
        __syncthreads();
    }

    const int h = bh & 15, b = bh >> 4;
    #pragma unroll
    for (int i = 0; i < 4; i++) {
        float vv[2][4];
        #pragma unroll
        for (int j = 0; j < 4; j++) upk2(c2[i][j], vv[0][j], vv[1][j]);
        #pragma unroll
        for (int hh = 0; hh < 2; hh++) {
            int n = n0 + ty*8 + 2*i + hh;
            int d0 = tx*4;
            if (MODE == 0) {
                float bt = g_beta[(size_t)bh * SEQ + n];
                float4 v4 = *(const float4*)(g_qkv + (size_t)(b*SEQ + n) * 3072 + 2048 + h*DH + d0);
                float4 o;
                o.x = bt * (v4.x - vv[hh][0]);
                o.y = bt * (v4.y - vv[hh][1]);
                o.z = bt * (v4.z - vv[hh][2]);
                o.w = bt * (v4.w - vv[hh][3]);
                *(float4*)(g_dv + (size_t)(bh*SEQ + n) * DH + d0) = o;
            } else {
                size_t base = (size_t)(b*SEQ + n) * DIMV + h*DH + d0;
                #pragma unroll
                for (int j = 0; j < 4; j += 2) {
                    float x0 = vv[hh][j], x1 = vv[hh][j+1];
                    __nv_bfloat16 h0 = __float2bfloat16(x0), h1 = __float2bfloat16(x1);
                    float l0 = x0 - __bfloat162float(h0), l1 = x1 - __bfloat162float(h1);
                    *(__nv_bfloat162*)(g_ah + base + j) = __halves2bfloat162(h0, h1);
                    *(__nv_bfloat162*)(g_al + base + j) =
                        __halves2bfloat162(__float2bfloat16(l0), __float2bfloat16(l1));
                }
            }
        }
    }
}

// ============================================================================
// wacc: partial W[s,d] = sum_n phik[n,s]*dv[n,d]; then deterministic reduce.
// ============================================================================
__global__ void __launch_bounds__(256)
wacc_kernel()
{
    __shared__ float Ph[32][132];
    __shared__ float Dvs[32][68];
    const int tid = threadIdx.x;
    const int ts = tid >> 4, td = tid & 15;
    const int bh = blockIdx.y;
    const int n0 = blockIdx.x * 512;

    unsigned long long c2[4][4];
    #pragma unroll
    for (int i = 0; i < 4; i++)
        #pragma unroll
        for (int j = 0; j < 4; j++) c2[i][j] = 0ULL;

    for (int nt = 0; nt < 16; ++nt) {
        int nb = n0 + nt * 32;
        #pragma unroll
        for (int i = 0; i < 4; i++) {
            int v = tid + i*256;
            int row = v >> 5, c4 = (v & 31) << 2;
            *(float4*)&Ph[row][c4] =
                *(const float4*)(g_phik + (size_t)(bh*SEQ + nb + row) * SDIM + c4);
        }
        #pragma unroll
        for (int i = 0; i < 2; i++) {
            int v = tid + i*256;
            int row = v >> 4, c4 = (v & 15) << 2;
            *(float4*)&Dvs[row][c4] =
                *(const float4*)(g_dv + (size_t)(bh*SEQ + nb + row) * DH + c4);
        }
        __syncthreads();
        #pragma unroll
        for (int nn = 0; nn < 32; ++nn) {
            float4 a0 = *(const float4*)&Ph[nn][ts*8];
            float4 a1 = *(const float4*)&Ph[nn][ts*8+4];
            float4 dq = *(const float4*)&Dvs[nn][td*4];
            unsigned long long am[4];
            am[0] = pk2(a0.x, a0.y); am[1] = pk2(a0.z, a0.w);
            am[2] = pk2(a1.x, a1.y); am[3] = pk2(a1.z, a1.w);
            float dj[4] = {dq.x, dq.y, dq.z, dq.w};
            #pragma unroll
            for (int j = 0; j < 4; j++) {
                unsigned long long bb = pk2(dj[j], dj[j]);
                fma2(c2[0][j], am[0], bb);
                fma2(c2[1][j], am[1], bb);
                fma2(c2[2][j], am[2], bb);
                fma2(c2[3][j], am[3], bb);
            }
        }
        __syncthreads();
    }

    float* wp = g_Wpart + ((size_t)blockIdx.x * BHTOT + bh) * (SDIM*DH);
    #pragma unroll
    for (int i = 0; i < 4; i++) {
        float vv[2][4];
        #pragma unroll
        for (int j = 0; j < 4; j++) upk2(c2[i][j], vv[0][j], vv[1][j]);
        #pragma unroll
        for (int hh = 0; hh < 2; hh++) {
            int s = ts*8 + 2*i + hh;
            *(float4*)(wp + s*DH + td*4) =
                make_float4(vv[hh][0], vv[hh][1], vv[hh][2], vv[hh][3]);
        }
    }
}

__global__ void __launch_bounds__(256)
wreduce_kernel(const float* __restrict__ W0)
{
    int idx = blockIdx.x * 256 + threadIdx.x;   // < 524288
    float s = W0[idx];
    #pragma unroll
    for (int c = 0; c < 8; c++) s += g_Wpart[(size_t)c * (BHTOT*SDIM*DH) + idx];
    g_W[idx] = s;
}

// ============================================================================
// LayerNorm over 1024, one row per block.
// ============================================================================
__global__ void __launch_bounds__(256)
ln_kernel(const float* __restrict__ gamma, const float* __restrict__ betaln,
          float* __restrict__ out)
{
    const int row = blockIdx.x, tid = threadIdx.x;
    float4 v = *(const float4*)(g_y + (size_t)row * DIMV + tid*4);
    float s = v.x + v.y + v.z + v.w;
    float q = v.x*v.x + v.y*v.y + v.z*v.z + v.w*v.w;
    #pragma unroll
    for (int o = 16; o; o >>= 1) {
        s += __shfl_xor_sync(0xffffffffu, s, o);
        q += __shfl_xor_sync(0xffffffffu, q, o);
    }
    __shared__ float ss[8], qq[8];
    int w = tid >> 5, l = tid & 31;
    if (l == 0) { ss[w] = s; qq[w] = q; }
    __syncthreads();
    float st = 0.f, qt = 0.f;
    #pragma unroll
    for (int i = 0; i < 8; i++) { st += ss[i]; qt += qq[i]; }
    float mu = st * (1.0f / DIMV);
    float var = qt * (1.0f / DIMV) - mu * mu;
    float rs = rsqrtf(var + 1e-5f);
    float4 g = *(const float4*)(gamma + tid*4);
    float4 bb = *(const float4*)(betaln + tid*4);
    float4 o;
    o.x = (v.x - mu) * rs * g.x + bb.x;
    o.y = (v.y - mu) * rs * g.y + bb.y;
    o.z = (v.z - mu) * rs * g.z + bb.z;
    o.w = (v.w - mu) * rs * g.w + bb.w;
    *(float4*)(out + (size_t)row * DIMV + tid*4) = o;
}

// ============================================================================
extern "C" void kernel_launch(void* const* d_in, const int* in_sizes, int n_in,
                              void* d_out, int out_size)
{
    (void)in_sizes; (void)n_in; (void)out_size;
    const float* x      = (const float*)d_in[0];
    const float* Wqkv   = (const float*)d_in[1];
    const float* Wbeta  = (const float*)d_in[2];
    const float* bbeta  = (const float*)d_in[3];
    const float* Wout   = (const float*)d_in[4];
    const float* bout   = (const float*)d_in[5];
    const float* gamma  = (const float*)d_in[6];
    const float* betaln = (const float*)d_in[7];
    const float* W0     = (const float*)d_in[8];
    float* out = (float*)d_out;

    float *p_qkv = nullptr, *p_y = nullptr;
    cudaGetSymbolAddress((void**)&p_qkv, g_qkv);
    cudaGetSymbolAddress((void**)&p_y,   g_y);
    __nv_bfloat16 *p_xh, *p_xl, *p_wqh, *p_wql, *p_woh, *p_wol, *p_ah, *p_al;
    cudaGetSymbolAddress((void**)&p_xh,  g_xh);
    cudaGetSymbolAddress((void**)&p_xl,  g_xl);
    cudaGetSymbolAddress((void**)&p_wqh, g_wqh);
    cudaGetSymbolAddress((void**)&p_wql, g_wql);
    cudaGetSymbolAddress((void**)&p_woh, g_woh);
    cudaGetSymbolAddress((void**)&p_wol, g_wol);
    cudaGetSymbolAddress((void**)&p_ah,  g_ah);
    cudaGetSymbolAddress((void**)&p_al,  g_al);

    cudaFuncSetAttribute(hmma_kernel<0>, cudaFuncAttributeMaxDynamicSharedMemorySize, SMEMB);
    cudaFuncSetAttribute(hmma_kernel<1>, cudaFuncAttributeMaxDynamicSharedMemorySize, SMEMB);

    // 0. bf16 hi/lo operand prep
    splitx_kernel<<<16384, 256>>>(x, p_xh, p_xl);
    wsplit_kernel<<<dim3(96, 32), 256>>>(Wqkv, p_wqh, p_wql, 3072);
    wsplit_kernel<<<dim3(32, 32), 256>>>(Wout, p_woh, p_wol, 1024);
    // 1. qkv = x @ Wqkv   (HMMA, 3-split bf16, 2 CTAs/SM, term-outer MMA order)
    hmma_kernel<0><<<dim3(24, 128), 256, SMEMB>>>(
        p_xh, p_xl, p_wqh, p_wql, p_qkv, 3072, nullptr, nullptr);
    // 2. beta = x @ Wbeta + bbeta
    beta_kernel<<<128, 128>>>(x, Wbeta, bbeta);
    // 3. dpfp feature maps
    dpfp_kernel<<<65536, 256>>>();
    // 4a. dv = beta * (v - phik @ W0)
    phiw_kernel<0><<<dim3(32, 64), 256>>>(W0);
    // 4b. W = W0 + phik^T @ dv
    wacc_kernel<<<dim3(8, 64), 256>>>();
    wreduce_kernel<<<2048, 256>>>(W0);
    // 4c. attn = phiq_scaled @ W  -> bf16 hi/lo
    phiw_kernel<1><<<dim3(32, 64), 256>>>(nullptr);
    // 5. y = attn @ Wout + bout + x   (HMMA)
    hmma_kernel<1><<<dim3(8, 128), 256, SMEMB>>>(
        p_ah, p_al, p_woh, p_wol, p_y, 1024, bout, x);
    // 6. LayerNorm -> out
    ln_kernel<<<16384, 256>>>(gamma, betaln, out);
}

// round 13
// speedup vs baseline: 1.3776x; 1.2390x over previous
#include <cuda_runtime.h>
#include <cuda_bf16.h>
#include <cstdint>

#define BATCH 4
#define SEQ   4096
#define DIMV  1024
#define NH    16
#define DH    64
#define SDIM  128
#define ROWS  (BATCH*SEQ)   // 16384
#define BHTOT (BATCH*NH)    // 64

// ---------------- scratch (device globals: no allocation allowed) ----------------
__device__ float g_qkv [(size_t)ROWS * 3072];          // 201 MB
__device__ float g_phiq[(size_t)BHTOT * SEQ * SDIM];   // 134 MB (scale folded in)
__device__ float g_phik[(size_t)BHTOT * SEQ * SDIM];   // 134 MB
__device__ float g_beta[(size_t)BHTOT * SEQ];
__device__ float g_dv  [(size_t)BHTOT * SEQ * DH];     // 67 MB
__device__ float g_W   [(size_t)BHTOT * SDIM * DH];
__device__ float g_Wpart[(size_t)8 * BHTOT * SDIM * DH];
__device__ float g_y   [(size_t)ROWS * DIMV];          // 64 MB

// bf16 operands for tensor-core GEMMs (A: hi only; B: hi+lo split)
__device__ __nv_bfloat16 g_xh[(size_t)ROWS * DIMV];
__device__ __nv_bfloat16 g_wqh[(size_t)3072 * DIMV];
__device__ __nv_bfloat16 g_wql[(size_t)3072 * DIMV];
__device__ __nv_bfloat16 g_woh[(size_t)DIMV * DIMV];
__device__ __nv_bfloat16 g_wol[(size_t)DIMV * DIMV];
__device__ __nv_bfloat16 g_ah[(size_t)ROWS * DIMV];

// ---------------- packed f32x2 helpers (Blackwell FFMA2) ----------------
__device__ __forceinline__ unsigned long long pk2(float lo, float hi) {
    unsigned long long r;
    asm("mov.b64 %0, {%1,%2};" : "=l"(r) : "f"(lo), "f"(hi));
    return r;
}
__device__ __forceinline__ void upk2(unsigned long long v, float &lo, float &hi) {
    asm("mov.b64 {%0,%1}, %2;" : "=f"(lo), "=f"(hi) : "l"(v));
}
__device__ __forceinline__ void fma2(unsigned long long &c, unsigned long long a, unsigned long long b) {
    asm("fma.rn.f32x2 %0, %1, %2, %0;" : "+l"(c) : "l"(a), "l"(b));
}

// ---------------- HMMA helpers (sm_80-class, legal on plain sm_103 target) ----------------
__device__ __forceinline__ uint32_t smem_u32(const void* p) {
    uint32_t r;
    asm("{ .reg .u64 t; cvta.to.shared.u64 t, %1; cvt.u32.u64 %0, t; }" : "=r"(r) : "l"(p));
    return r;
}
__device__ __forceinline__ void cpasync16(uint32_t dst, const void* src) {
    asm volatile("cp.async.cg.shared.global [%0], [%1], 16;" :: "r"(dst), "l"(src) : "memory");
}
#define CP_COMMIT() asm volatile("cp.async.commit_group;" ::: "memory")

__device__ __forceinline__ void ldsm4(uint32_t* r, uint32_t addr) {
    asm volatile("ldmatrix.sync.aligned.m8n8.x4.shared.b16 {%0,%1,%2,%3}, [%4];"
                 : "=r"(r[0]), "=r"(r[1]), "=r"(r[2]), "=r"(r[3]) : "r"(addr));
}
__device__ __forceinline__ void mma16816(float* c, const uint32_t* a, const uint32_t* b) {
    asm volatile("mma.sync.aligned.m16n8k16.row.col.f32.bf16.bf16.f32 "
                 "{%0,%1,%2,%3}, {%4,%5,%6,%7}, {%8,%9}, {%0,%1,%2,%3};"
                 : "+f"(c[0]), "+f"(c[1]), "+f"(c[2]), "+f"(c[3])
                 : "r"(a[0]), "r"(a[1]), "r"(a[2]), "r"(a[3]), "r"(b[0]), "r"(b[1]));
}

// K-chunk 32, row stride 40 bf16 (80B): 8-row ldmatrix phases step 20 banks
// mod 32 -> all 32 banks covered, conflict-free.
#define KCH    32
#define RSTR   40
#define TILEB  (128*RSTR*2)          // 10240 B
#define BUFB   (3*TILEB)             // Ah,Bh,Bl = 30720 B
#define NSTAGE 3
#define SMEMB  (NSTAGE*BUFB)         // 92160 B/CTA -> 2 CTAs/SM
#define NKC    (1024/KCH)            // 32 chunks

// ============================================================================
// HMMA GEMM (2-term split): C[M,N] = Ah@Bh^T + Ah@Bl^T = Ah@(Bh+Bl)^T, fp32 out.
// Ah: [M,1024] bf16 K-major. Bh/Bl: [N,1024] bf16 K-major (pre-transposed,
// hi/lo split so B is fp32-accurate; residual error = a_lo*b ~ 2^-9, damped
// by the pipeline to ~1e-4 final rel_err).
// CTA tile 128x128, 8 warps (2x4), warp tile 64x32, K-chunk 32,
// 3-stage cp.async pipeline, ONE __syncthreads per chunk, 2 CTAs/SM.
// EPI: += bias[col] + resid[row,col].
// ============================================================================
template<int EPI>
__global__ void __launch_bounds__(256, 2)
hmma_kernel(const __nv_bfloat16* __restrict__ Ah,
            const __nv_bfloat16* __restrict__ Bh, const __nv_bfloat16* __restrict__ Bl,
            float* __restrict__ C, int N,
            const float* __restrict__ bias, const float* __restrict__ resid)
{
    extern __shared__ char dsm[];
    const uint32_t sbase = smem_u32(dsm);
    const int tid  = threadIdx.x;
    const int lane = tid & 31, wid = tid >> 5;
    const int wm = wid >> 2, wn = wid & 3;           // warp grid 2 (m) x 4 (n)
    const int bm = blockIdx.y * 128, bn = blockIdx.x * 128;

    // ldmatrix per-lane byte offsets within a tile (RSTR-element row stride)
    const uint32_t aoffb = (uint32_t)(((wm * 64 + (lane & 15)) * RSTR + ((lane >> 4) << 3)) * 2);
    const uint32_t boffb = (uint32_t)(((wn * 32 + ((lane >> 4) << 3) + (lane & 7)) * RSTR + (lane & 8)) * 2);

    float acc[4][4][4];
    #pragma unroll
    for (int i = 0; i < 4; i++)
        #pragma unroll
        for (int j = 0; j < 4; j++)
            #pragma unroll
            for (int q = 0; q < 4; q++) acc[i][j][q] = 0.f;

    auto load_chunk = [&](int kt, int buf) {
        const uint32_t sb = sbase + buf * BUFB;
        const int kco = kt * KCH;
        #pragma unroll
        for (int i = 0; i < 2; i++) {
            const int v = tid + i * 256;                 // 0..511
            const int row = v >> 2, c4 = v & 3;          // row 0..127, 16B chunk 0..3
            const uint32_t so = (uint32_t)((row * RSTR + c4 * 8) * 2);
            const size_t ao = (size_t)(bm + row) * 1024 + kco + c4 * 8;
            const size_t bo = (size_t)(bn + row) * 1024 + kco + c4 * 8;
            cpasync16(sb + 0 * TILEB + so, Ah + ao);
            cpasync16(sb + 1 * TILEB + so, Bh + bo);
            cpasync16(sb + 2 * TILEB + so, Bl + bo);
        }
        CP_COMMIT();
    };

    // prologue: two chunks in flight
    load_chunk(0, 0);
    load_chunk(1, 1);

    int rb = 0;   // buffer holding chunk kt
    int wb = 2;   // buffer to receive chunk kt+2
    #pragma unroll 1
    for (int kt = 0; kt < NKC; ++kt) {
        if (kt < NKC - 1) asm volatile("cp.async.wait_group 1;" ::: "memory");
        else              asm volatile("cp.async.wait_group 0;" ::: "memory");
        __syncthreads();                 // chunk kt visible; all warps done with kt-1
        if (kt + 2 < NKC) load_chunk(kt + 2, wb);   // overwrites buffer consumed at kt-1

        const uint32_t sb = sbase + rb * BUFB;
        #pragma unroll
        for (int ks = 0; ks < KCH / 16; ++ks) {
            uint32_t bH[4][2], bL[4][2];
            #pragma unroll
            for (int pr = 0; pr < 2; pr++) {
                const uint32_t bd = sb + 1 * TILEB + boffb + (uint32_t)((pr * 16 * RSTR + ks * 16) * 2);
                uint32_t r[4];
                ldsm4(r, bd);
                bH[pr*2][0] = r[0]; bH[pr*2][1] = r[1];
                bH[pr*2+1][0] = r[2]; bH[pr*2+1][1] = r[3];
                ldsm4(r, bd + TILEB);
                bL[pr*2][0] = r[0]; bL[pr*2][1] = r[1];
                bL[pr*2+1][0] = r[2]; bL[pr*2+1][1] = r[3];
            }
            #pragma unroll
            for (int mi = 0; mi < 4; mi++) {
                uint32_t aH[4];
                const uint32_t ad = sb + aoffb + (uint32_t)((mi * 16 * RSTR + ks * 16) * 2);
                ldsm4(aH, ad);
                // writers of acc[mi][ni] separated by 4 independent MMAs
                #pragma unroll
                for (int ni = 0; ni < 4; ni++) mma16816(acc[mi][ni], aH, bH[ni]);
                #pragma unroll
                for (int ni = 0; ni < 4; ni++) mma16816(acc[mi][ni], aH, bL[ni]);
            }
        }
        rb = (rb == 2) ? 0 : rb + 1;
        wb = (wb == 2) ? 0 : wb + 1;
    }

    // epilogue: acc frag mapping c0,c1=(m=lane/4, n=(lane%4)*2), c2,c3=(m+8)
    #pragma unroll
    for (int mi = 0; mi < 4; mi++)
        #pragma unroll
        for (int ni = 0; ni < 4; ni++) {
            const int m0 = bm + wm * 64 + mi * 16 + (lane >> 2);
            const int n0 = bn + wn * 32 + ni * 8 + (lane & 3) * 2;
            const size_t o0 = (size_t)m0 * N + n0;
            const size_t o1 = o0 + (size_t)8 * N;
            float c0 = acc[mi][ni][0], c1 = acc[mi][ni][1];
            float c2 = acc[mi][ni][2], c3 = acc[mi][ni][3];
            if (EPI) {
                const float b0v = bias[n0], b1v = bias[n0 + 1];
                c0 += b0v + resid[o0];     c1 += b1v + resid[o0 + 1];
                c2 += b0v + resid[o1];     c3 += b1v + resid[o1 + 1];
            }
            *(float2*)(C + o0) = make_float2(c0, c1);
            *(float2*)(C + o1) = make_float2(c2, c3);
        }
}

// ============================================================================
// fp32 -> bf16 (hi only; A operands)
// ============================================================================
__global__ void __launch_bounds__(256)
tobf16_kernel(const float* __restrict__ src, __nv_bfloat16* __restrict__ hi)
{
    size_t idx = (size_t)blockIdx.x * 256 + threadIdx.x;
    float4 v = ((const float4*)src)[idx];
    __nv_bfloat16 h0 = __float2bfloat16(v.x), h1 = __float2bfloat16(v.y);
    __nv_bfloat16 h2 = __float2bfloat16(v.z), h3 = __float2bfloat16(v.w);
    ((__nv_bfloat162*)hi)[2 * idx]     = __halves2bfloat162(h0, h1);
    ((__nv_bfloat162*)hi)[2 * idx + 1] = __halves2bfloat162(h2, h3);
}

// ============================================================================
// W [1024,Ncols] fp32 -> W^T [Ncols,1024] bf16 hi/lo (transpose + split)
// ============================================================================
__global__ void __launch_bounds__(256)
wsplit_kernel(const float* __restrict__ W, __nv_bfloat16* __restrict__ hi,
              __nv_bfloat16* __restrict__ lo, int Ncols)
{
    __shared__ float t[32][33];
    const int nx = blockIdx.x * 32, ky = blockIdx.y * 32;
    const int txx = threadIdx.x & 31, tyy = threadIdx.x >> 5;   // 32 x 8
    #pragma unroll
    for (int i = 0; i < 4; i++)
        t[tyy + i * 8][txx] = W[(size_t)(ky + tyy + i * 8) * Ncols + nx + txx];
    __syncthreads();
    #pragma unroll
    for (int i = 0; i < 4; i++) {
        const int n = nx + tyy + i * 8;
        const int k = ky + txx;
        const float v = t[txx][tyy + i * 8];
        __nv_bfloat16 hh = __float2bfloat16(v);
        hi[(size_t)n * 1024 + k] = hh;
        lo[(size_t)n * 1024 + k] = __float2bfloat16(v - __bfloat162float(hh));
    }
}

// ============================================================================
// beta = x @ Wbeta + bbeta  -> g_beta[(b*16+h)*SEQ + n]
// ============================================================================
__global__ void __launch_bounds__(128)
beta_kernel(const float* __restrict__ X, const float* __restrict__ Wb,
            const float* __restrict__ bb)
{
    __shared__ float Xs[32][132];
    __shared__ float Wbs[32][16];
    const int tid = threadIdx.x;
    const int tx = tid & 3;
    const int ty = tid >> 2;
    const int bm = blockIdx.x * 128;

    unsigned long long c2[2][4];
    #pragma unroll
    for (int i = 0; i < 2; i++)
        #pragma unroll
        for (int j = 0; j < 4; j++) c2[i][j] = 0ULL;

    for (int kt = 0; kt < 32; ++kt) {
        int k0 = kt * 32;
        #pragma unroll
        for (int i = 0; i < 8; i++) {
            float4 xv = *(const float4*)(X + (size_t)(bm + tid) * DIMV + k0 + i*4);
            Xs[i*4+0][tid] = xv.x; Xs[i*4+1][tid] = xv.y;
            Xs[i*4+2][tid] = xv.z; Xs[i*4+3][tid] = xv.w;
        }
        {
            float4 wv = *(const float4*)(Wb + (size_t)(k0 + (tid >> 2)) * NH + (tid & 3) * 4);
            *(float4*)&Wbs[tid >> 2][(tid & 3) * 4] = wv;
        }
        __syncthreads();
        #pragma unroll
        for (int k = 0; k < 32; k++) {
            float4 a = *(const float4*)&Xs[k][ty*4];
            float4 b = *(const float4*)&Wbs[k][tx*4];
            unsigned long long am[2] = { pk2(a.x, a.y), pk2(a.z, a.w) };
            float bj[4] = {b.x, b.y, b.z, b.w};
            #pragma unroll
            for (int j = 0; j < 4; j++) {
                unsigned long long b2 = pk2(bj[j], bj[j]);
                fma2(c2[0][j], am[0], b2);
                fma2(c2[1][j], am[1], b2);
            }
        }
        __syncthreads();
    }

    #pragma unroll
    for (int i = 0; i < 2; i++) {
        float vv[2][4];
        #pragma unroll
        for (int j = 0; j < 4; j++) upk2(c2[i][j], vv[0][j], vv[1][j]);
        #pragma unroll
        for (int hh = 0; hh < 2; hh++) {
            int r = bm + ty*4 + 2*i + hh;
            int b = r >> 12, n = r & 4095;
            #pragma unroll
            for (int j = 0; j < 4; j++) {
                int h = tx*4 + j;
                g_beta[(size_t)(b*NH + h) * SEQ + n] = vv[hh][j] + bb[h];
            }
        }
    }
}

// ============================================================================
// dpfp feature maps (L1-normalized; q gets SCALE folded)
// ============================================================================
__global__ void __launch_bounds__(256)
dpfp_kernel()
{
    __shared__ float cat[8][128];
    const int tid = threadIdx.x;
    const int w = tid >> 5, l = tid & 31;
    unsigned int task = blockIdx.x * 8u + w;   // < 524288
    int qk = task >> 18;
    unsigned int rem = task & 0x3FFFFu;
    int bh = rem >> 12;
    int n  = rem & 4095;
    int b = bh >> 4, h = bh & 15;

    const float* src = g_qkv + (size_t)(b*SEQ + n) * 3072 + qk * 1024 + h * DH;
    float f0 = src[l];
    float f1 = src[l + 32];
    cat[w][l]      = fmaxf(f0, 0.f);
    cat[w][l + 32] = fmaxf(f1, 0.f);
    cat[w][l + 64] = fmaxf(-f0, 0.f);
    cat[w][l + 96] = fmaxf(-f1, 0.f);
    __syncwarp();
    float p0 = cat[w][l]      * cat[w][(l + 127) & 127];
    float p1 = cat[w][l + 32] * cat[w][l + 31];
    float p2 = cat[w][l + 64] * cat[w][l + 63];
    float p3 = cat[w][l + 96] * cat[w][l + 95];
    float s = p0 + p1 + p2 + p3;
    #pragma unroll
    for (int o = 16; o; o >>= 1) s += __shfl_xor_sync(0xffffffffu, s, o);
    float inv = 1.0f / s;
    float* dst;
    if (qk == 0) { inv *= 0.125f; dst = g_phiq; }
    else         { dst = g_phik; }
    dst += (size_t)(bh * SEQ + n) * SDIM;
    dst[l]      = p0 * inv;
    dst[l + 32] = p1 * inv;
    dst[l + 64] = p2 * inv;
    dst[l + 96] = p3 * inv;
}

// ============================================================================
// phiw: per-(b,h) GEMM [128n x 128s] @ [128s x 64d], W resident in shared.
// MODE 0: dv = beta * (v - phik@W0)
// MODE 1: attn = phiq_scaled @ W  -> bf16 (hi only; feeds hmma<1> A side)
// ============================================================================
template<int MODE>
__global__ void __launch_bounds__(256)
phiw_kernel(const float* __restrict__ WmIn)
{
    __shared__ float Ws[128][68];
    __shared__ float As[16][132];
    const int tid = threadIdx.x;
    const int tx = tid & 15, ty = tid >> 4;
    const int bh = blockIdx.y;
    const int n0 = blockIdx.x * 128;

    const float* wsrc = (MODE == 0 ? WmIn : (const float*)g_W) + (size_t)bh * (SDIM*DH);
    #pragma unroll
    for (int i = 0; i < 8; i++) {
        int v = tid + i*256;
        int row = v >> 4, c4 = (v & 15) << 2;
        *(float4*)&Ws[row][c4] = *(const float4*)(wsrc + row*DH + c4);
    }
    const float* phib = (MODE == 0 ? g_phik : g_phiq) + (size_t)(bh*SEQ + n0) * SDIM;
    const int arow = tid >> 2, ac4 = (tid & 3) << 2;

    unsigned long long c2[4][4];
    #pragma unroll
    for (int i = 0; i < 4; i++)
        #pragma unroll
        for (int j = 0; j < 4; j++) c2[i][j] = 0ULL;

    for (int kt = 0; kt < 8; ++kt) {
        int k0 = kt * 16;
        float4 v0 = *(const float4*)(phib + (size_t)arow        * SDIM + k0 + ac4);
        float4 v1 = *(const float4*)(phib + (size_t)(arow + 64) * SDIM + k0 + ac4);
        As[ac4+0][arow]    = v0.x; As[ac4+1][arow]    = v0.y;
        As[ac4+2][arow]    = v0.z; As[ac4+3][arow]    = v0.w;
        As[ac4+0][arow+64] = v1.x; As[ac4+1][arow+64] = v1.y;
        As[ac4+2][arow+64] = v1.z; As[ac4+3][arow+64] = v1.w;
        __syncthreads();
        #pragma unroll
        for (int k = 0; k < 16; k++) {
            float4 a0 = *(const float4*)&As[k][ty*8];
            float4 a1 = *(const float4*)&As[k][ty*8+4];
            float4 bq = *(const float4*)&Ws[k0 + k][tx*4];
            unsigned long long am[4];
            am[0] = pk2(a0.x, a0.y); am[1] = pk2(a0.z, a0.w);
            am[2] = pk2(a1.x, a1.y); am[3] = pk2(a1.z, a1.w);
            float bj[4] = {bq.x, bq.y, bq.z, bq.w};
            #pragma unroll
            for (int j = 0; j < 4; j++) {
                unsigned long long bb = pk2(bj[j], bj[j]);
                fma2(c2[0][j], am[0], bb);
                fma2(c2[1][j], am[1], bb);
                fma2(c2[2][j], am[2], bb);
                fma2(c2[3][j], am[3], bb);
            }
        }
        __syncthreads();
    }

    const int h = bh & 15, b = bh >> 4;
    #pragma unroll
    for (int i = 0; i < 4; i++) {
        float vv[2][4];
        #pragma unroll
        for (int j = 0; j < 4; j++) upk2(c2[i][j], vv[0][j], vv[1][j]);
        #pragma unroll
        for (int hh = 0; hh < 2; hh++) {
            int n = n0 + ty*8 + 2*i + hh;
            int d0 = tx*4;
            if (MODE == 0) {
                float bt = g_beta[(size_t)bh * SEQ + n];
                float4 v4 = *(const float4*)(g_qkv + (size_t)(b*SEQ + n) * 3072 + 2048 + h*DH + d0);
                float4 o;
                o.x = bt * (v4.x - vv[hh][0]);
                o.y = bt * (v4.y - vv[hh][1]);
                o.z = bt * (v4.z - vv[hh][2]);
                o.w = bt * (v4.w - vv[hh][3]);
                *(float4*)(g_dv + (size_t)(bh*SEQ + n) * DH + d0) = o;
            } else {
                size_t base = (size_t)(b*SEQ + n) * DIMV + h*DH + d0;
                #pragma unroll
                for (int j = 0; j < 4; j += 2) {
                    __nv_bfloat16 h0 = __float2bfloat16(vv[hh][j]);
                    __nv_bfloat16 h1 = __float2bfloat16(vv[hh][j+1]);
                    *(__nv_bfloat162*)(g_ah + base + j) = __halves2bfloat162(h0, h1);
                }
            }
        }
    }
}

// ============================================================================
// wacc: partial W[s,d] = sum_n phik[n,s]*dv[n,d]; then deterministic reduce.
// ============================================================================
__global__ void __launch_bounds__(256)
wacc_kernel()
{
    __shared__ float Ph[32][132];
    __shared__ float Dvs[32][68];
    const int tid = threadIdx.x;
    const int ts = tid >> 4, td = tid & 15;
    const int bh = blockIdx.y;
    const int n0 = blockIdx.x * 512;

    unsigned long long c2[4][4];
    #pragma unroll
    for (int i = 0; i < 4; i++)
        #pragma unroll
        for (int j = 0; j < 4; j++) c2[i][j] = 0ULL;

    for (int nt = 0; nt < 16; ++nt) {
        int nb = n0 + nt * 32;
        #pragma unroll
        for (int i = 0; i < 4; i++) {
            int v = tid + i*256;
            int row = v >> 5, c4 = (v & 31) << 2;
            *(float4*)&Ph[row][c4] =
                *(const float4*)(g_phik + (size_t)(bh*SEQ + nb + row) * SDIM + c4);
        }
        #pragma unroll
        for (int i = 0; i < 2; i++) {
            int v = tid + i*256;
            int row = v >> 4, c4 = (v & 15) << 2;
            *(float4*)&Dvs[row][c4] =
                *(const float4*)(g_dv + (size_t)(bh*SEQ + nb + row) * DH + c4);
        }
        __syncthreads();
        #pragma unroll
        for (int nn = 0; nn < 32; ++nn) {
            float4 a0 = *(const float4*)&Ph[nn][ts*8];
            float4 a1 = *(const float4*)&Ph[nn][ts*8+4];
            float4 dq = *(const float4*)&Dvs[nn][td*4];
            unsigned long long am[4];
            am[0] = pk2(a0.x, a0.y); am[1] = pk2(a0.z, a0.w);
            am[2] = pk2(a1.x, a1.y); am[3] = pk2(a1.z, a1.w);
            float dj[4] = {dq.x, dq.y, dq.z, dq.w};
            #pragma unroll
            for (int j = 0; j < 4; j++) {
                unsigned long long bb = pk2(dj[j], dj[j]);
                fma2(c2[0][j], am[0], bb);
                fma2(c2[1][j], am[1], bb);
                fma2(c2[2][j], am[2], bb);
                fma2(c2[3][j], am[3], bb);
            }
        }
        __syncthreads();
    }

    float* wp = g_Wpart + ((size_t)blockIdx.x * BHTOT + bh) * (SDIM*DH);
    #pragma unroll
    for (int i = 0; i < 4; i++) {
        float vv[2][4];
        #pragma unroll
        for (int j = 0; j < 4; j++) upk2(c2[i][j], vv[0][j], vv[1][j]);
        #pragma unroll
        for (int hh = 0; hh < 2; hh++) {
            int s = ts*8 + 2*i + hh;
            *(float4*)(wp + s*DH + td*4) =
                make_float4(vv[hh][0], vv[hh][1], vv[hh][2], vv[hh][3]);
        }
    }
}

__global__ void __launch_bounds__(256)
wreduce_kernel(const float* __restrict__ W0)
{
    int idx = blockIdx.x * 256 + threadIdx.x;   // < 524288
    float s = W0[idx];
    #pragma unroll
    for (int c = 0; c < 8; c++) s += g_Wpart[(size_t)c * (BHTOT*SDIM*DH) + idx];
    g_W[idx] = s;
}

// ============================================================================
// LayerNorm over 1024, one row per block.
// ============================================================================
__global__ void __launch_bounds__(256)
ln_kernel(const float* __restrict__ gamma, const float* __restrict__ betaln,
          float* __restrict__ out)
{
    const int row = blockIdx.x, tid = threadIdx.x;
    float4 v = *(const float4*)(g_y + (size_t)row * DIMV + tid*4);
    float s = v.x + v.y + v.z + v.w;
    float q = v.x*v.x + v.y*v.y + v.z*v.z + v.w*v.w;
    #pragma unroll
    for (int o = 16; o; o >>= 1) {
        s += __shfl_xor_sync(0xffffffffu, s, o);
        q += __shfl_xor_sync(0xffffffffu, q, o);
    }
    __shared__ float ss[8], qq[8];
    int w = tid >> 5, l = tid & 31;
    if (l == 0) { ss[w] = s; qq[w] = q; }
    __syncthreads();
    float st = 0.f, qt = 0.f;
    #pragma unroll
    for (int i = 0; i < 8; i++) { st += ss[i]; qt += qq[i]; }
    float mu = st * (1.0f / DIMV);
    float var = qt * (1.0f / DIMV) - mu * mu;
    float rs = rsqrtf(var + 1e-5f);
    float4 g = *(const float4*)(gamma + tid*4);
    float4 bb = *(const float4*)(betaln + tid*4);
    float4 o;
    o.x = (v.x - mu) * rs * g.x + bb.x;
    o.y = (v.y - mu) * rs * g.y + bb.y;
    o.z = (v.z - mu) * rs * g.z + bb.z;
    o.w = (v.w - mu) * rs * g.w + bb.w;
    *(float4*)(out + (size_t)row * DIMV + tid*4) = o;
}

// ============================================================================
extern "C" void kernel_launch(void* const* d_in, const int* in_sizes, int n_in,
                              void* d_out, int out_size)
{
    (void)in_sizes; (void)n_in; (void)out_size;
    const float* x      = (const float*)d_in[0];
    const float* Wqkv   = (const float*)d_in[1];
    const float* Wbeta  = (const float*)d_in[2];
    const float* bbeta  = (const float*)d_in[3];
    const float* Wout   = (const float*)d_in[4];
    const float* bout   = (const float*)d_in[5];
    const float* gamma  = (const float*)d_in[6];
    const float* betaln = (const float*)d_in[7];
    const float* W0     = (const float*)d_in[8];
    float* out = (float*)d_out;

    float *p_qkv = nullptr, *p_y = nullptr;
    cudaGetSymbolAddress((void**)&p_qkv, g_qkv);
    cudaGetSymbolAddress((void**)&p_y,   g_y);
    __nv_bfloat16 *p_xh, *p_wqh, *p_wql, *p_woh, *p_wol, *p_ah;
    cudaGetSymbolAddress((void**)&p_xh,  g_xh);
    cudaGetSymbolAddress((void**)&p_wqh, g_wqh);
    cudaGetSymbolAddress((void**)&p_wql, g_wql);
    cudaGetSymbolAddress((void**)&p_woh, g_woh);
    cudaGetSymbolAddress((void**)&p_wol, g_wol);
    cudaGetSymbolAddress((void**)&p_ah,  g_ah);

    cudaFuncSetAttribute(hmma_kernel<0>, cudaFuncAttributeMaxDynamicSharedMemorySize, SMEMB);
    cudaFuncSetAttribute(hmma_kernel<1>, cudaFuncAttributeMaxDynamicSharedMemorySize, SMEMB);

    // 0. bf16 operand prep (A: hi only; B: hi/lo split)
    tobf16_kernel<<<16384, 256>>>(x, p_xh);
    wsplit_kernel<<<dim3(96, 32), 256>>>(Wqkv, p_wqh, p_wql, 3072);
    wsplit_kernel<<<dim3(32, 32), 256>>>(Wout, p_woh, p_wol, 1024);
    // 1. qkv = x @ Wqkv   (HMMA, 2-term split, 3-stage, 2 CTAs/SM)
    hmma_kernel<0><<<dim3(24, 128), 256, SMEMB>>>(
        p_xh, p_wqh, p_wql, p_qkv, 3072, nullptr, nullptr);
    // 2. beta = x @ Wbeta + bbeta
    beta_kernel<<<128, 128>>>(x, Wbeta, bbeta);
    // 3. dpfp feature maps
    dpfp_kernel<<<65536, 256>>>();
    // 4a. dv = beta * (v - phik @ W0)
    phiw_kernel<0><<<dim3(32, 64), 256>>>(W0);
    // 4b. W = W0 + phik^T @ dv
    wacc_kernel<<<dim3(8, 64), 256>>>();
    wreduce_kernel<<<2048, 256>>>(W0);
    // 4c. attn = phiq_scaled @ W  -> bf16 hi
    phiw_kernel<1><<<dim3(32, 64), 256>>>(nullptr);
    // 5. y = attn @ Wout + bout + x   (HMMA)
    hmma_kernel<1><<<dim3(8, 128), 256, SMEMB>>>(
        p_ah, p_woh, p_wol, p_y, 1024, bout, x);
    // 6. LayerNorm -> out
    ln_kernel<<<16384, 256>>>(gamma, betaln, out);
}

// round 17
// speedup vs baseline: 1.4081x; 1.0221x over previous
#include <cuda_runtime.h>
#include <cuda_bf16.h>
#include <cstdint>

#define BATCH 4
#define SEQ   4096
#define DIMV  1024
#define NH    16
#define DH    64
#define SDIM  128
#define ROWS  (BATCH*SEQ)   // 16384
#define BHTOT (BATCH*NH)    // 64

// ---------------- scratch (device globals: no allocation allowed) ----------------
__device__ float g_qkv [(size_t)ROWS * 3072];          // 201 MB
__device__ float g_phiq[(size_t)BHTOT * SEQ * SDIM];   // 134 MB (scale folded in)
__device__ float g_phik[(size_t)BHTOT * SEQ * SDIM];   // 134 MB
__device__ float g_beta[(size_t)BHTOT * SEQ];
__device__ float g_dv  [(size_t)BHTOT * SEQ * DH];     // 67 MB
__device__ float g_W   [(size_t)BHTOT * SDIM * DH];
__device__ float g_Wpart[(size_t)8 * BHTOT * SDIM * DH];
__device__ float g_y   [(size_t)ROWS * DIMV];          // 64 MB

// bf16 operands for tensor-core GEMMs (A: hi only; B: hi+lo split)
__device__ __nv_bfloat16 g_xh[(size_t)ROWS * DIMV];
__device__ __nv_bfloat16 g_wqh[(size_t)3072 * DIMV];
__device__ __nv_bfloat16 g_wql[(size_t)3072 * DIMV];
__device__ __nv_bfloat16 g_woh[(size_t)DIMV * DIMV];
__device__ __nv_bfloat16 g_wol[(size_t)DIMV * DIMV];
__device__ __nv_bfloat16 g_ah[(size_t)ROWS * DIMV];

// ---------------- packed f32x2 helpers (Blackwell FFMA2) ----------------
__device__ __forceinline__ unsigned long long pk2(float lo, float hi) {
    unsigned long long r;
    asm("mov.b64 %0, {%1,%2};" : "=l"(r) : "f"(lo), "f"(hi));
    return r;
}
__device__ __forceinline__ void upk2(unsigned long long v, float &lo, float &hi) {
    asm("mov.b64 {%0,%1}, %2;" : "=f"(lo), "=f"(hi) : "l"(v));
}
__device__ __forceinline__ void fma2(unsigned long long &c, unsigned long long a, unsigned long long b) {
    asm("fma.rn.f32x2 %0, %1, %2, %0;" : "+l"(c) : "l"(a), "l"(b));
}

// ---------------- HMMA helpers (sm_80-class, legal on plain sm_103 target) ----------------
__device__ __forceinline__ uint32_t smem_u32(const void* p) {
    uint32_t r;
    asm("{ .reg .u64 t; cvta.to.shared.u64 t, %1; cvt.u32.u64 %0, t; }" : "=r"(r) : "l"(p));
    return r;
}
__device__ __forceinline__ void cpasync16(uint32_t dst, const void* src) {
    asm volatile("cp.async.cg.shared.global [%0], [%1], 16;" :: "r"(dst), "l"(src) : "memory");
}
#define CP_COMMIT() asm volatile("cp.async.commit_group;" ::: "memory")

__device__ __forceinline__ void ldsm4(uint32_t* r, uint32_t addr) {
    asm volatile("ldmatrix.sync.aligned.m8n8.x4.shared.b16 {%0,%1,%2,%3}, [%4];"
                 : "=r"(r[0]), "=r"(r[1]), "=r"(r[2]), "=r"(r[3]) : "r"(addr));
}
__device__ __forceinline__ void mma16816(float* c, const uint32_t* a, const uint32_t* b) {
    asm volatile("mma.sync.aligned.m16n8k16.row.col.f32.bf16.bf16.f32 "
                 "{%0,%1,%2,%3}, {%4,%5,%6,%7}, {%8,%9}, {%0,%1,%2,%3};"
                 : "+f"(c[0]), "+f"(c[1]), "+f"(c[2]), "+f"(c[3])
                 : "r"(a[0]), "r"(a[1]), "r"(a[2]), "r"(a[3]), "r"(b[0]), "r"(b[1]));
}

// K-chunk 64, row stride 72 bf16 (144B = 36 banks): 8-row ldmatrix phases step
// 4 banks mod 32 -> rows cover banks 0..31 exactly, conflict-free.
// Only the first 64 elements (8 x 16B) of each smem row are loaded from global;
// the 16B pad (elements 64..71) is never read by ldmatrix (max column = 64).
#define KCH    64
#define RSTR   72
#define TILEB  (128*RSTR*2)          // 18432 B
#define BUFB   (3*TILEB)             // Ah,Bh,Bl = 55296 B
#define NSTAGE 2
#define SMEMB  (NSTAGE*BUFB)         // 110592 B/CTA -> 2 CTAs/SM (221KB < 228KB)
#define NKC    (1024/KCH)            // 16 chunks

// ============================================================================
// HMMA GEMM (2-term split): C[M,N] = Ah@Bh^T + Ah@Bl^T = Ah@(Bh+Bl)^T, fp32 out.
// Ah: [M,1024] bf16 K-major. Bh/Bl: [N,1024] bf16 K-major (pre-transposed,
// hi/lo split so B is fp32-accurate; residual error = a_lo*b ~ 2^-9, damped
// by the pipeline to ~1e-4 final rel_err).
// CTA tile 128x128, 8 warps (2x4), warp tile 64x32, K-chunk 64,
// 2-stage cp.async pipeline, ONE __syncthreads per chunk, 2 CTAs/SM.
// EPI: += bias[col] + resid[row,col].
// ============================================================================
template<int EPI>
__global__ void __launch_bounds__(256, 2)
hmma_kernel(const __nv_bfloat16* __restrict__ Ah,
            const __nv_bfloat16* __restrict__ Bh, const __nv_bfloat16* __restrict__ Bl,
            float* __restrict__ C, int N,
            const float* __restrict__ bias, const float* __restrict__ resid)
{
    extern __shared__ char dsm[];
    const uint32_t sbase = smem_u32(dsm);
    const int tid  = threadIdx.x;
    const int lane = tid & 31, wid = tid >> 5;
    const int wm = wid >> 2, wn = wid & 3;           // warp grid 2 (m) x 4 (n)
    const int bm = blockIdx.y * 128, bn = blockIdx.x * 128;

    // ldmatrix per-lane byte offsets within a tile (RSTR-element row stride)
    const uint32_t aoffb = (uint32_t)(((wm * 64 + (lane & 15)) * RSTR + ((lane >> 4) << 3)) * 2);
    const uint32_t boffb = (uint32_t)(((wn * 32 + ((lane >> 4) << 3) + (lane & 7)) * RSTR + (lane & 8)) * 2);

    float acc[4][4][4];
    #pragma unroll
    for (int i = 0; i < 4; i++)
        #pragma unroll
        for (int j = 0; j < 4; j++)
            #pragma unroll
            for (int q = 0; q < 4; q++) acc[i][j][q] = 0.f;

    // 3 tiles x 128 rows x 8 16B-chunks/row = 3072 cp.async, 256 threads x 4 iters.
    // Global reads stay within [kco, kco+64) per row -- pad column NOT loaded.
    auto load_chunk = [&](int kt, int buf) {
        const uint32_t sb = sbase + buf * BUFB;
        const int kco = kt * KCH;
        #pragma unroll
        for (int i = 0; i < 4; i++) {
            const int v = tid + i * 256;                 // 0..1023
            const int row = v >> 3, c8 = v & 7;          // row 0..127, 16B chunk 0..7
            const uint32_t so = (uint32_t)((row * RSTR + c8 * 8) * 2);
            const size_t ao = (size_t)(bm + row) * 1024 + kco + c8 * 8;
            const size_t bo = (size_t)(bn + row) * 1024 + kco + c8 * 8;
            cpasync16(sb + 0 * TILEB + so, Ah + ao);
            cpasync16(sb + 1 * TILEB + so, Bh + bo);
            cpasync16(sb + 2 * TILEB + so, Bl + bo);
        }
        CP_COMMIT();
    };

    load_chunk(0, 0);

    #pragma unroll 1
    for (int kt = 0; kt < NKC; ++kt) {
        const int rb = kt & 1;
        asm volatile("cp.async.wait_group 0;" ::: "memory");   // chunk kt landed
        __syncthreads();                                       // all warps done with kt-1's buffer
        if (kt + 1 < NKC) load_chunk(kt + 1, rb ^ 1);          // overlaps compute of kt

        const uint32_t sb = sbase + rb * BUFB;
        #pragma unroll
        for (int ks = 0; ks < KCH / 16; ++ks) {
            uint32_t bH[4][2], bL[4][2];
            #pragma unroll
            for (int pr = 0; pr < 2; pr++) {
                const uint32_t bd = sb + 1 * TILEB + boffb + (uint32_t)((pr * 16 * RSTR + ks * 16) * 2);
                uint32_t r[4];
                ldsm4(r, bd);
                bH[pr*2][0] = r[0]; bH[pr*2][1] = r[1];
                bH[pr*2+1][0] = r[2]; bH[pr*2+1][1] = r[3];
                ldsm4(r, bd + TILEB);
                bL[pr*2][0] = r[0]; bL[pr*2][1] = r[1];
                bL[pr*2+1][0] = r[2]; bL[pr*2+1][1] = r[3];
            }
            #pragma unroll
            for (int mi = 0; mi < 4; mi++) {
                uint32_t aH[4];
                const uint32_t ad = sb + aoffb + (uint32_t)((mi * 16 * RSTR + ks * 16) * 2);
                ldsm4(aH, ad);
                // writers of acc[mi][ni] separated by 4 independent MMAs
                #pragma unroll
                for (int ni = 0; ni < 4; ni++) mma16816(acc[mi][ni], aH, bH[ni]);
                #pragma unroll
                for (int ni = 0; ni < 4; ni++) mma16816(acc[mi][ni], aH, bL[ni]);
            }
        }
    }

    // epilogue: acc frag mapping c0,c1=(m=lane/4, n=(lane%4)*2), c2,c3=(m+8)
    #pragma unroll
    for (int mi = 0; mi < 4; mi++)
        #pragma unroll
        for (int ni = 0; ni < 4; ni++) {
            const int m0 = bm + wm * 64 + mi * 16 + (lane >> 2);
            const int n0 = bn + wn * 32 + ni * 8 + (lane & 3) * 2;
            const size_t o0 = (size_t)m0 * N + n0;
            const size_t o1 = o0 + (size_t)8 * N;
            float c0 = acc[mi][ni][0], c1 = acc[mi][ni][1];
            float c2 = acc[mi][ni][2], c3 = acc[mi][ni][3];
            if (EPI) {
                const float b0v = bias[n0], b1v = bias[n0 + 1];
                c0 += b0v + resid[o0];     c1 += b1v + resid[o0 + 1];
                c2 += b0v + resid[o1];     c3 += b1v + resid[o1 + 1];
            }
            *(float2*)(C + o0) = make_float2(c0, c1);
            *(float2*)(C + o1) = make_float2(c2, c3);
        }
}

// ============================================================================
// fp32 -> bf16 (hi only; A operands)
// ============================================================================
__global__ void __launch_bounds__(256)
tobf16_kernel(const float* __restrict__ src, __nv_bfloat16* __restrict__ hi)
{
    size_t idx = (size_t)blockIdx.x * 256 + threadIdx.x;
    float4 v = ((const float4*)src)[idx];
    __nv_bfloat16 h0 = __float2bfloat16(v.x), h1 = __float2bfloat16(v.y);
    __nv_bfloat16 h2 = __float2bfloat16(v.z), h3 = __float2bfloat16(v.w);
    ((__nv_bfloat162*)hi)[2 * idx]     = __halves2bfloat162(h0, h1);
    ((__nv_bfloat162*)hi)[2 * idx + 1] = __halves2bfloat162(h2, h3);
}

// ============================================================================
// W [1024,Ncols] fp32 -> W^T [Ncols,1024] bf16 hi/lo (transpose + split)
// ============================================================================
__global__ void __launch_bounds__(256)
wsplit_kernel(const float* __restrict__ W, __nv_bfloat16* __restrict__ hi,
              __nv_bfloat16* __restrict__ lo, int Ncols)
{
    __shared__ float t[32][33];
    const int nx = blockIdx.x * 32, ky = blockIdx.y * 32;
    const int txx = threadIdx.x & 31, tyy = threadIdx.x >> 5;   // 32 x 8
    #pragma unroll
    for (int i = 0; i < 4; i++)
        t[tyy + i * 8][txx] = W[(size_t)(ky + tyy + i * 8) * Ncols + nx + txx];
    __syncthreads();
    #pragma unroll
    for (int i = 0; i < 4; i++) {
        const int n = nx + tyy + i * 8;
        const int k = ky + txx;
        const float v = t[txx][tyy + i * 8];
        __nv_bfloat16 hh = __float2bfloat16(v);
        hi[(size_t)n * 1024 + k] = hh;
        lo[(size_t)n * 1024 + k] = __float2bfloat16(v - __bfloat162float(hh));
    }
}

// ============================================================================
// beta = x @ Wbeta + bbeta  -> g_beta[(b*16+h)*SEQ + n]
// ============================================================================
__global__ void __launch_bounds__(128)
beta_kernel(const float* __restrict__ X, const float* __restrict__ Wb,
            const float* __restrict__ bb)
{
    __shared__ float Xs[32][132];
    __shared__ float Wbs[32][16];
    const int tid = threadIdx.x;
    const int tx = tid & 3;
    const int ty = tid >> 2;
    const int bm = blockIdx.x * 128;

    unsigned long long c2[2][4];
    #pragma unroll
    for (int i = 0; i < 2; i++)
        #pragma unroll
        for (int j = 0; j < 4; j++) c2[i][j] = 0ULL;

    for (int kt = 0; kt < 32; ++kt) {
        int k0 = kt * 32;
        #pragma unroll
        for (int i = 0; i < 8; i++) {
            float4 xv = *(const float4*)(X + (size_t)(bm + tid) * DIMV + k0 + i*4);
            Xs[i*4+0][tid] = xv.x; Xs[i*4+1][tid] = xv.y;
            Xs[i*4+2][tid] = xv.z; Xs[i*4+3][tid] = xv.w;
        }
        {
            float4 wv = *(const float4*)(Wb + (size_t)(k0 + (tid >> 2)) * NH + (tid & 3) * 4);
            *(float4*)&Wbs[tid >> 2][(tid & 3) * 4] = wv;
        }
        __syncthreads();
        #pragma unroll
        for (int k = 0; k < 32; k++) {
            float4 a = *(const float4*)&Xs[k][ty*4];
            float4 b = *(const float4*)&Wbs[k][tx*4];
            unsigned long long am[2] = { pk2(a.x, a.y), pk2(a.z, a.w) };
            float bj[4] = {b.x, b.y, b.z, b.w};
            #pragma unroll
            for (int j = 0; j < 4; j++) {
                unsigned long long b2 = pk2(bj[j], bj[j]);
                fma2(c2[0][j], am[0], b2);
                fma2(c2[1][j], am[1], b2);
            }
        }
        __syncthreads();
    }

    #pragma unroll
    for (int i = 0; i < 2; i++) {
        float vv[2][4];
        #pragma unroll
        for (int j = 0; j < 4; j++) upk2(c2[i][j], vv[0][j], vv[1][j]);
        #pragma unroll
        for (int hh = 0; hh < 2; hh++) {
            int r = bm + ty*4 + 2*i + hh;
            int b = r >> 12, n = r & 4095;
            #pragma unroll
            for (int j = 0; j < 4; j++) {
                int h = tx*4 + j;
                g_beta[(size_t)(b*NH + h) * SEQ + n] = vv[hh][j] + bb[h];
            }
        }
    }
}

// ============================================================================
// dpfp feature maps (L1-normalized; q gets SCALE folded)
// ============================================================================
__global__ void __launch_bounds__(256)
dpfp_kernel()
{
    __shared__ float cat[8][128];
    const int tid = threadIdx.x;
    const int w = tid >> 5, l = tid & 31;
    unsigned int task = blockIdx.x * 8u + w;   // < 524288
    int qk = task >> 18;
    unsigned int rem = task & 0x3FFFFu;
    int bh = rem >> 12;
    int n  = rem & 4095;
    int b = bh >> 4, h = bh & 15;

    const float* src = g_qkv + (size_t)(b*SEQ + n) * 3072 + qk * 1024 + h * DH;
    float f0 = src[l];
    float f1 = src[l + 32];
    cat[w][l]      = fmaxf(f0, 0.f);
    cat[w][l + 32] = fmaxf(f1, 0.f);
    cat[w][l + 64] = fmaxf(-f0, 0.f);
    cat[w][l + 96] = fmaxf(-f1, 0.f);
    __syncwarp();
    float p0 = cat[w][l]      * cat[w][(l + 127) & 127];
    float p1 = cat[w][l + 32] * cat[w][l + 31];
    float p2 = cat[w][l + 64] * cat[w][l + 63];
    float p3 = cat[w][l + 96] * cat[w][l + 95];
    float s = p0 + p1 + p2 + p3;
    #pragma unroll
    for (int o = 16; o; o >>= 1) s += __shfl_xor_sync(0xffffffffu, s, o);
    float inv = 1.0f / s;
    float* dst;
    if (qk == 0) { inv *= 0.125f; dst = g_phiq; }
    else         { dst = g_phik; }
    dst += (size_t)(bh * SEQ + n) * SDIM;
    dst[l]      = p0 * inv;
    dst[l + 32] = p1 * inv;
    dst[l + 64] = p2 * inv;
    dst[l + 96] = p3 * inv;
}

// ============================================================================
// phiw: per-(b,h) GEMM [128n x 128s] @ [128s x 64d], W resident in shared.
// MODE 0: dv = beta * (v - phik@W0)
// MODE 1: attn = phiq_scaled @ W  -> bf16 (hi only; feeds hmma<1> A side)
// ============================================================================
template<int MODE>
__global__ void __launch_bounds__(256)
phiw_kernel(const float* __restrict__ WmIn)
{
    __shared__ float Ws[128][68];
    __shared__ float As[16][132];
    const int tid = threadIdx.x;
    const int tx = tid & 15, ty = tid >> 4;
    const int bh = blockIdx.y;
    const int n0 = blockIdx.x * 128;

    const float* wsrc = (MODE == 0 ? WmIn : (const float*)g_W) + (size_t)bh * (SDIM*DH);
    #pragma unroll
    for (int i = 0; i < 8; i++) {
        int v = tid + i*256;
        int row = v >> 4, c4 = (v & 15) << 2;
        *(float4*)&Ws[row][c4] = *(const float4*)(wsrc + row*DH + c4);
    }
    const float* phib = (MODE == 0 ? g_phik : g_phiq) + (size_t)(bh*SEQ + n0) * SDIM;
    const int arow = tid >> 2, ac4 = (tid & 3) << 2;

    unsigned long long c2[4][4];
    #pragma unroll
    for (int i = 0; i < 4; i++)
        #pragma unroll
        for (int j = 0; j < 4; j++) c2[i][j] = 0ULL;

    for (int kt = 0; kt < 8; ++kt) {
        int k0 = kt * 16;
        float4 v0 = *(const float4*)(phib + (size_t)arow        * SDIM + k0 + ac4);
        float4 v1 = *(const float4*)(phib + (size_t)(arow + 64) * SDIM + k0 + ac4);
        As[ac4+0][arow]    = v0.x; As[ac4+1][arow]    = v0.y;
        As[ac4+2][arow]    = v0.z; As[ac4+3][arow]    = v0.w;
        As[ac4+0][arow+64] = v1.x; As[ac4+1][arow+64] = v1.y;
        As[ac4+2][arow+64] = v1.z; As[ac4+3][arow+64] = v1.w;
        __syncthreads();
        #pragma unroll
        for (int k = 0; k < 16; k++) {
            float4 a0 = *(const float4*)&As[k][ty*8];
            float4 a1 = *(const float4*)&As[k][ty*8+4];
            float4 bq = *(const float4*)&Ws[k0 + k][tx*4];
            unsigned long long am[4];
            am[0] = pk2(a0.x, a0.y); am[1] = pk2(a0.z, a0.w);
            am[2] = pk2(a1.x, a1.y); am[3] = pk2(a1.z, a1.w);
            float bj[4] = {bq.x, bq.y, bq.z, bq.w};
            #pragma unroll
            for (int j = 0; j < 4; j++) {
                unsigned long long bb = pk2(bj[j], bj[j]);
                fma2(c2[0][j], am[0], bb);
                fma2(c2[1][j], am[1], bb);
                fma2(c2[2][j], am[2], bb);
                fma2(c2[3][j], am[3], bb);
            }
        }
        __syncthreads();
    }

    const int h = bh & 15, b = bh >> 4;
    #pragma unroll
    for (int i = 0; i < 4; i++) {
        float vv[2][4];
        #pragma unroll
        for (int j = 0; j < 4; j++) upk2(c2[i][j], vv[0][j], vv[1][j]);
        #pragma unroll
        for (int hh = 0; hh < 2; hh++) {
            int n = n0 + ty*8 + 2*i + hh;
            int d0 = tx*4;
            if (MODE == 0) {
                float bt = g_beta[(size_t)bh * SEQ + n];
                float4 v4 = *(const float4*)(g_qkv + (size_t)(b*SEQ + n) * 3072 + 2048 + h*DH + d0);
                float4 o;
                o.x = bt * (v4.x - vv[hh][0]);
                o.y = bt * (v4.y - vv[hh][1]);
                o.z = bt * (v4.z - vv[hh][2]);
                o.w = bt * (v4.w - vv[hh][3]);
                *(float4*)(g_dv + (size_t)(bh*SEQ + n) * DH + d0) = o;
            } else {
                size_t base = (size_t)(b*SEQ + n) * DIMV + h*DH + d0;
                #pragma unroll
                for (int j = 0; j < 4; j += 2) {
                    __nv_bfloat16 h0 = __float2bfloat16(vv[hh][j]);
                    __nv_bfloat16 h1 = __float2bfloat16(vv[hh][j+1]);
                    *(__nv_bfloat162*)(g_ah + base + j) = __halves2bfloat162(h0, h1);
                }
            }
        }
    }
}

// ============================================================================
// wacc: partial W[s,d] = sum_n phik[n,s]*dv[n,d]; then deterministic reduce.
// ============================================================================
__global__ void __launch_bounds__(256)
wacc_kernel()
{
    __shared__ float Ph[32][132];
    __shared__ float Dvs[32][68];
    const int tid = threadIdx.x;
    const int ts = tid >> 4, td = tid & 15;
    const int bh = blockIdx.y;
    const int n0 = blockIdx.x * 512;

    unsigned long long c2[4][4];
    #pragma unroll
    for (int i = 0; i < 4; i++)
        #pragma unroll
        for (int j = 0; j < 4; j++) c2[i][j] = 0ULL;

    for (int nt = 0; nt < 16; ++nt) {
        int nb = n0 + nt * 32;
        #pragma unroll
        for (int i = 0; i < 4; i++) {
            int v = tid + i*256;
            int row = v >> 5, c4 = (v & 31) << 2;
            *(float4*)&Ph[row][c4] =
                *(const float4*)(g_phik + (size_t)(bh*SEQ + nb + row) * SDIM + c4);
        }
        #pragma unroll
        for (int i = 0; i < 2; i++) {
            int v = tid + i*256;
            int row = v >> 4, c4 = (v & 15) << 2;
            *(float4*)&Dvs[row][c4] =
                *(const float4*)(g_dv + (size_t)(bh*SEQ + nb + row) * DH + c4);
        }
        __syncthreads();
        #pragma unroll
        for (int nn = 0; nn < 32; ++nn) {
            float4 a0 = *(const float4*)&Ph[nn][ts*8];
            float4 a1 = *(const float4*)&Ph[nn][ts*8+4];
            float4 dq = *(const float4*)&Dvs[nn][td*4];
            unsigned long long am[4];
            am[0] = pk2(a0.x, a0.y); am[1] = pk2(a0.z, a0.w);
            am[2] = pk2(a1.x, a1.y); am[3] = pk2(a1.z, a1.w);
            float dj[4] = {dq.x, dq.y, dq.z, dq.w};
            #pragma unroll
            for (int j = 0; j < 4; j++) {
                unsigned long long bb = pk2(dj[j], dj[j]);
                fma2(c2[0][j], am[0], bb);
                fma2(c2[1][j], am[1], bb);
                fma2(c2[2][j], am[2], bb);
                fma2(c2[3][j], am[3], bb);
            }
        }
        __syncthreads();
    }

    float* wp = g_Wpart + ((size_t)blockIdx.x * BHTOT + bh) * (SDIM*DH);
    #pragma unroll
    for (int i = 0; i < 4; i++) {
        float vv[2][4];
        #pragma unroll
        for (int j = 0; j < 4; j++) upk2(c2[i][j], vv[0][j], vv[1][j]);
        #pragma unroll
        for (int hh = 0; hh < 2; hh++) {
            int s = ts*8 + 2*i + hh;
            *(float4*)(wp + s*DH + td*4) =
                make_float4(vv[hh][0], vv[hh][1], vv[hh][2], vv[hh][3]);
        }
    }
}

__global__ void __launch_bounds__(256)
wreduce_kernel(const float* __restrict__ W0)
{
    int idx = blockIdx.x * 256 + threadIdx.x;   // < 524288
    float s = W0[idx];
    #pragma unroll
    for (int c = 0; c < 8; c++) s += g_Wpart[(size_t)c * (BHTOT*SDIM*DH) + idx];
    g_W[idx] = s;
}

// ============================================================================
// LayerNorm over 1024, one row per block.
// ============================================================================
__global__ void __launch_bounds__(256)
ln_kernel(const float* __restrict__ gamma, const float* __restrict__ betaln,
          float* __restrict__ out)
{
    const int row = blockIdx.x, tid = threadIdx.x;
    float4 v = *(const float4*)(g_y + (size_t)row * DIMV + tid*4);
    float s = v.x + v.y + v.z + v.w;
    float q = v.x*v.x + v.y*v.y + v.z*v.z + v.w*v.w;
    #pragma unroll
    for (int o = 16; o; o >>= 1) {
        s += __shfl_xor_sync(0xffffffffu, s, o);
        q += __shfl_xor_sync(0xffffffffu, q, o);
    }
    __shared__ float ss[8], qq[8];
    int w = tid >> 5, l = tid & 31;
    if (l == 0) { ss[w] = s; qq[w] = q; }
    __syncthreads();
    float st = 0.f, qt = 0.f;
    #pragma unroll
    for (int i = 0; i < 8; i++) { st += ss[i]; qt += qq[i]; }
    float mu = st * (1.0f / DIMV);
    float var = qt * (1.0f / DIMV) - mu * mu;
    float rs = rsqrtf(var + 1e-5f);
    float4 g = *(const float4*)(gamma + tid*4);
    float4 bb = *(const float4*)(betaln + tid*4);
    float4 o;
    o.x = (v.x - mu) * rs * g.x + bb.x;
    o.y = (v.y - mu) * rs * g.y + bb.y;
    o.z = (v.z - mu) * rs * g.z + bb.z;
    o.w = (v.w - mu) * rs * g.w + bb.w;
    *(float4*)(out + (size_t)row * DIMV + tid*4) = o;
}

// ============================================================================
extern "C" void kernel_launch(void* const* d_in, const int* in_sizes, int n_in,
                              void* d_out, int out_size)
{
    (void)in_sizes; (void)n_in; (void)out_size;
    const float* x      = (const float*)d_in[0];
    const float* Wqkv   = (const float*)d_in[1];
    const float* Wbeta  = (const float*)d_in[2];
    const float* bbeta  = (const float*)d_in[3];
    const float* Wout   = (const float*)d_in[4];
    const float* bout   = (const float*)d_in[5];
    const float* gamma  = (const float*)d_in[6];
    const float* betaln = (const float*)d_in[7];
    const float* W0     = (const float*)d_in[8];
    float* out = (float*)d_out;

    float *p_qkv = nullptr, *p_y = nullptr;
    cudaGetSymbolAddress((void**)&p_qkv, g_qkv);
    cudaGetSymbolAddress((void**)&p_y,   g_y);
    __nv_bfloat16 *p_xh, *p_wqh, *p_wql, *p_woh, *p_wol, *p_ah;
    cudaGetSymbolAddress((void**)&p_xh,  g_xh);
    cudaGetSymbolAddress((void**)&p_wqh, g_wqh);
    cudaGetSymbolAddress((void**)&p_wql, g_wql);
    cudaGetSymbolAddress((void**)&p_woh, g_woh);
    cudaGetSymbolAddress((void**)&p_wol, g_wol);
    cudaGetSymbolAddress((void**)&p_ah,  g_ah);

    cudaFuncSetAttribute(hmma_kernel<0>, cudaFuncAttributeMaxDynamicSharedMemorySize, SMEMB);
    cudaFuncSetAttribute(hmma_kernel<1>, cudaFuncAttributeMaxDynamicSharedMemorySize, SMEMB);

    // 0. bf16 operand prep (A: hi only; B: hi/lo split)
    tobf16_kernel<<<16384, 256>>>(x, p_xh);
    wsplit_kernel<<<dim3(96, 32), 256>>>(Wqkv, p_wqh, p_wql, 3072);
    wsplit_kernel<<<dim3(32, 32), 256>>>(Wout, p_woh, p_wol, 1024);
    // 1. qkv = x @ Wqkv   (HMMA, 2-term split, KCH=64, 2 CTAs/SM)
    hmma_kernel<0><<<dim3(24, 128), 256, SMEMB>>>(
        p_xh, p_wqh, p_wql, p_qkv, 3072, nullptr, nullptr);
    // 2. beta = x @ Wbeta + bbeta
    beta_kernel<<<128, 128>>>(x, Wbeta, bbeta);
    // 3. dpfp feature maps
    dpfp_kernel<<<65536, 256>>>();
    // 4a. dv = beta * (v - phik @ W0)
    phiw_kernel<0><<<dim3(32, 64), 256>>>(W0);
    // 4b. W = W0 + phik^T @ dv
    wacc_kernel<<<dim3(8, 64), 256>>>();
    wreduce_kernel<<<2048, 256>>>(W0);
    // 4c. attn = phiq_scaled @ W  -> bf16 hi
    phiw_kernel<1><<<dim3(32, 64), 256>>>(nullptr);
    // 5. y = attn @ Wout + bout + x   (HMMA)
    hmma_kernel<1><<<dim3(8, 128), 256, SMEMB>>>(
        p_ah, p_woh, p_wol, p_y, 1024, bout, x);
    // 6. LayerNorm -> out
    ln_kernel<<<16384, 256>>>(gamma, betaln, out);
}